// round 1
// baseline (speedup 1.0000x reference)
#include <cuda_runtime.h>
#include <cuda_bf16.h>
#include <cstdint>

#define BB 4
#define SS 2048
#define EE 1024
#define HH 16
#define DD 64
#define M_TOT (BB * SS)        // 8192

__device__ float g_q[BB * HH * SS * DD];
__device__ float g_k[BB * HH * SS * DD];
__device__ float g_v[BB * HH * SS * DD];
__device__ float g_y[BB * SS * EE];

#define GBM 128
#define GBN 128
#define GBK 16

template <int MODE>
__global__ __launch_bounds__(256, 2) void sgemm_kernel(
    const float* __restrict__ A_in, const float* __restrict__ B_in,
    float* __restrict__ C, int M, int N, int K)
{
    __shared__ float As[GBK][GBM];
    __shared__ float Bs[GBK][GBN];

    const float* A = (MODE == 1) ? g_y : A_in;

    const int tid = threadIdx.x;
    const int tx = tid & 15;
    const int ty = tid >> 4;
    const int m0 = blockIdx.y * GBM;
    const int n0 = blockIdx.x * GBN;

    float acc[8][8];
#pragma unroll
    for (int i = 0; i < 8; i++)
#pragma unroll
        for (int j = 0; j < 8; j++) acc[i][j] = 0.0f;

    for (int k0 = 0; k0 < K; k0 += GBK) {
#pragma unroll
        for (int q = 0; q < 2; q++) {
            int lin = tid * 2 + q;
            int row = lin >> 2;
            int c4  = lin & 3;
            float4 av = *(const float4*)&A[(size_t)(m0 + row) * K + k0 + c4 * 4];
            As[c4 * 4 + 0][row] = av.x;
            As[c4 * 4 + 1][row] = av.y;
            As[c4 * 4 + 2][row] = av.z;
            As[c4 * 4 + 3][row] = av.w;
        }
#pragma unroll
        for (int q = 0; q < 2; q++) {
            int lin = tid * 2 + q;
            int row = lin >> 5;
            int c4  = lin & 31;
            *(float4*)&Bs[row][c4 * 4] =
                *(const float4*)&B_in[(size_t)(k0 + row) * N + n0 + c4 * 4];
        }
        __syncthreads();

#pragma unroll
        for (int kk = 0; kk < GBK; kk++) {
            float a[8], b[8];
            *(float4*)&a[0] = *(float4*)&As[kk][ty * 8];
            *(float4*)&a[4] = *(float4*)&As[kk][ty * 8 + 4];
            *(float4*)&b[0] = *(float4*)&Bs[kk][tx * 8];
            *(float4*)&b[4] = *(float4*)&Bs[kk][tx * 8 + 4];
#pragma unroll
            for (int i = 0; i < 8; i++)
#pragma unroll
                for (int j = 0; j < 8; j++) acc[i][j] += a[i] * b[j];
        }
        __syncthreads();
    }

    if (MODE == 0) {
        const int sec   = n0 >> 10;
        float* dst_base = (sec == 0) ? g_q : (sec == 1) ? g_k : g_v;
        const int nbase = n0 + tx * 8;
        const int c     = nbase & 1023;
        const int h     = c >> 6;
        const int d0    = c & 63;
#pragma unroll
        for (int i = 0; i < 8; i++) {
            int m = m0 + ty * 8 + i;
            int b = m >> 11;
            int s = m & 2047;
            size_t idx = (((size_t)(b * HH + h) * SS) + s) * DD + d0;
            *(float4*)&dst_base[idx]     = make_float4(acc[i][0], acc[i][1], acc[i][2], acc[i][3]);
            *(float4*)&dst_base[idx + 4] = make_float4(acc[i][4], acc[i][5], acc[i][6], acc[i][7]);
        }
    } else {
#pragma unroll
        for (int i = 0; i < 8; i++) {
            int m = m0 + ty * 8 + i;
            size_t idx = (size_t)m * N + n0 + tx * 8;
            *(float4*)&C[idx]     = make_float4(acc[i][0], acc[i][1], acc[i][2], acc[i][3]);
            *(float4*)&C[idx + 4] = make_float4(acc[i][4], acc[i][5], acc[i][6], acc[i][7]);
        }
    }
}

#define FP 68
#define FLASH_SMEM (4 * 64 * FP * 4)

__global__ __launch_bounds__(256) void flash_kernel(float* __restrict__ gout)
{
    const int qt = blockIdx.x;
    const int bh = blockIdx.y;
    const int q0 = qt * 64;
    const float* qb = g_q + (size_t)bh * SS * DD;
    const float* kb = g_k + (size_t)bh * SS * DD;
    const float* vb = g_v + (size_t)bh * SS * DD;
    const int b = bh >> 4, h = bh & 15;
    float* ob = gout + (size_t)b * SS * EE + h * DD;

    extern __shared__ float sm[];
    float* Qt = sm;
    float* Kt = sm + 64 * FP;
    float* Vs = sm + 2 * 64 * FP;
    float* Ps = sm + 3 * 64 * FP;

    const int tid = threadIdx.x;
    const int tx = tid & 15;
    const int ty = tid >> 4;

#pragma unroll
    for (int u = 0; u < 16; u++) {
        int lin = u * 256 + tid;
        int r = lin >> 6, d = lin & 63;
        Qt[d * FP + r] = qb[(size_t)(q0 + r) * DD + d];
    }

    float acc[4][4];
#pragma unroll
    for (int i = 0; i < 4; i++)
#pragma unroll
        for (int j = 0; j < 4; j++) acc[i][j] = 0.0f;
    float m_i[4] = {-1e30f, -1e30f, -1e30f, -1e30f};
    float l_i[4] = {0.0f, 0.0f, 0.0f, 0.0f};
    const float scale = 0.125f;

    for (int jt = 0; jt <= qt; jt++) {
        __syncthreads();
        const int k0 = jt * 64;
#pragma unroll
        for (int u = 0; u < 16; u++) {
            int lin = u * 256 + tid;
            int c = lin >> 6, d = lin & 63;
            size_t gidx = (size_t)(k0 + c) * DD + d;
            Kt[d * FP + c] = kb[gidx];
            Vs[c * FP + d] = vb[gidx];
        }
        __syncthreads();

        float s[4][4];
#pragma unroll
        for (int i = 0; i < 4; i++)
#pragma unroll
            for (int j = 0; j < 4; j++) s[i][j] = 0.0f;
#pragma unroll 8
        for (int d = 0; d < 64; d++) {
            float4 av = *(float4*)&Qt[d * FP + ty * 4];
            float4 bv = *(float4*)&Kt[d * FP + tx * 4];
            float a[4] = {av.x, av.y, av.z, av.w};
            float bb2[4] = {bv.x, bv.y, bv.z, bv.w};
#pragma unroll
            for (int i = 0; i < 4; i++)
#pragma unroll
                for (int j = 0; j < 4; j++) s[i][j] += a[i] * bb2[j];
        }

        const bool diag = (jt == qt);
#pragma unroll
        for (int i = 0; i < 4; i++) {
            int r = ty * 4 + i;
#pragma unroll
            for (int j = 0; j < 4; j++) {
                float v = s[i][j] * scale;
                if (diag && (tx * 4 + j) > r) v = -1e30f;
                s[i][j] = v;
            }
        }

#pragma unroll
        for (int i = 0; i < 4; i++) {
            float mx = fmaxf(fmaxf(s[i][0], s[i][1]), fmaxf(s[i][2], s[i][3]));
            mx = fmaxf(mx, __shfl_xor_sync(0xffffffffu, mx, 1));
            mx = fmaxf(mx, __shfl_xor_sync(0xffffffffu, mx, 2));
            mx = fmaxf(mx, __shfl_xor_sync(0xffffffffu, mx, 4));
            mx = fmaxf(mx, __shfl_xor_sync(0xffffffffu, mx, 8));
            float mnew = fmaxf(m_i[i], mx);
            float corr = __expf(m_i[i] - mnew);
            m_i[i] = mnew;
            float rs = 0.0f;
#pragma unroll
            for (int j = 0; j < 4; j++) {
                float p = __expf(s[i][j] - mnew);
                s[i][j] = p;
                rs += p;
            }
            rs += __shfl_xor_sync(0xffffffffu, rs, 1);
            rs += __shfl_xor_sync(0xffffffffu, rs, 2);
            rs += __shfl_xor_sync(0xffffffffu, rs, 4);
            rs += __shfl_xor_sync(0xffffffffu, rs, 8);
            l_i[i] = l_i[i] * corr + rs;
#pragma unroll
            for (int j = 0; j < 4; j++) acc[i][j] *= corr;
            *(float4*)&Ps[(ty * 4 + i) * FP + tx * 4] =
                make_float4(s[i][0], s[i][1], s[i][2], s[i][3]);
        }
        __syncthreads();

#pragma unroll 8
        for (int kk = 0; kk < 64; kk++) {
            float4 vv = *(float4*)&Vs[kk * FP + tx * 4];
            float vj[4] = {vv.x, vv.y, vv.z, vv.w};
#pragma unroll
            for (int i = 0; i < 4; i++) {
                float p = Ps[(ty * 4 + i) * FP + kk];
#pragma unroll
                for (int j = 0; j < 4; j++) acc[i][j] += p * vj[j];
            }
        }
    }

#pragma unroll
    for (int i = 0; i < 4; i++) {
        float inv = 1.0f / l_i[i];
        int sgl = q0 + ty * 4 + i;
        *(float4*)&ob[(size_t)sgl * EE + tx * 4] =
            make_float4(acc[i][0] * inv, acc[i][1] * inv,
                        acc[i][2] * inv, acc[i][3] * inv);
    }
}

extern "C" void kernel_launch(void* const* d_in, const int* in_sizes, int n_in,
                              void* d_out, int out_size)
{
    const float* x      = (const float*)d_in[0];
    const float* w_attn = (const float*)d_in[1];
    const float* w_proj = (const float*)d_in[2];
    float* out = (float*)d_out;

    // 1. QKV GEMM -> g_q/g_k/g_v
    {
        dim3 grid(3 * EE / GBN, M_TOT / GBM);
        sgemm_kernel<0><<<grid, 256>>>(x, w_attn, nullptr, M_TOT, 3 * EE, EE);
    }

    // 2. Flash attention -> g_y (device global; kernel needs its address)
    {
        cudaFuncSetAttribute(flash_kernel,
                             cudaFuncAttributeMaxDynamicSharedMemorySize,
                             FLASH_SMEM);
        float* gy_ptr = nullptr;
        cudaGetSymbolAddress((void**)&gy_ptr, g_y);
        dim3 grid(SS / 64, BB * HH);
        flash_kernel<<<grid, 256, FLASH_SMEM>>>(gy_ptr);
    }

    // 3. Proj GEMM: g_y @ w_proj -> out
    {
        dim3 grid(EE / GBN, M_TOT / GBM);
        sgemm_kernel<1><<<grid, 256>>>(nullptr, w_proj, out, M_TOT, EE, EE);
    }
}

// round 2
// speedup vs baseline: 1.0079x; 1.0079x over previous
#include <cuda_runtime.h>
#include <cuda_bf16.h>
#include <cstdint>

#define BB 4
#define SS 2048
#define EE 1024
#define HH 16
#define DD 64
#define M_TOT (BB * SS)        // 8192

__device__ float g_q[BB * HH * SS * DD];
__device__ float g_k[BB * HH * SS * DD];
__device__ float g_v[BB * HH * SS * DD];
__device__ float g_y[BB * SS * EE];

// ---------------------------------------------------------------------------
// 3xTF32 tensor-core GEMM: C[M,N] = A[M,K] @ B[K,N] at ~fp32 accuracy.
// Block 128x128x16, 8 warps, warp tile 64x32 (mma.m16n8k8).
// Smem pads: A k-stride 20 (banks: (lane/4)*20 + lane%4 all distinct mod 32),
//            B n-stride 136 (banks: (lane%4)*8 + lane/4 + c, distinct).
// ---------------------------------------------------------------------------
#define TBM 128
#define TBN 128
#define TBK 16
#define APAD 20
#define BPAD 136

__device__ __forceinline__ uint32_t f2tf32(float x) {
    uint32_t r;
    asm("cvt.rna.tf32.f32 %0, %1;" : "=r"(r) : "f"(x));
    return r;
}

__device__ __forceinline__ void mma_tf32(float* c, const uint32_t* a,
                                         uint32_t b0, uint32_t b1) {
    asm volatile(
        "mma.sync.aligned.m16n8k8.row.col.f32.tf32.tf32.f32 "
        "{%0,%1,%2,%3}, {%4,%5,%6,%7}, {%8,%9}, {%0,%1,%2,%3};\n"
        : "+f"(c[0]), "+f"(c[1]), "+f"(c[2]), "+f"(c[3])
        : "r"(a[0]), "r"(a[1]), "r"(a[2]), "r"(a[3]), "r"(b0), "r"(b1));
}

template <int MODE>
__global__ __launch_bounds__(256, 2) void tf32_gemm(
    const float* __restrict__ A_in, const float* __restrict__ B_in,
    float* __restrict__ C, int M, int N, int K)
{
    __shared__ uint32_t As[2][TBM * APAD];   // [0]=big [1]=small
    __shared__ uint32_t Bs[2][TBK * BPAD];

    const float* A = (MODE == 1) ? g_y : A_in;

    const int tid  = threadIdx.x;
    const int lane = tid & 31;
    const int warp = tid >> 5;
    const int wm   = warp & 1;       // 0..1 -> 64-row slab
    const int wn   = warp >> 1;      // 0..3 -> 32-col slab
    const int m0   = blockIdx.y * TBM;
    const int n0   = blockIdx.x * TBN;

    float acc[4][4][4];
#pragma unroll
    for (int i = 0; i < 4; i++)
#pragma unroll
        for (int j = 0; j < 4; j++)
#pragma unroll
            for (int t = 0; t < 4; t++) acc[i][j][t] = 0.0f;

    const int rA = wm * 64 + (lane >> 2);   // fragment row base (A)
    const int cA = lane & 3;                // fragment col base (A, k)
    const int cB = wn * 32 + (lane >> 2);   // fragment col base (B, n)
    const int rB = lane & 3;                // fragment row base (B, k)

    for (int k0 = 0; k0 < K; k0 += TBK) {
        __syncthreads();   // protect previous iteration's reads

        // ---- load + split A tile (128x16) ----
#pragma unroll
        for (int q = 0; q < 2; q++) {
            int lin  = tid * 2 + q;
            int arow = lin >> 2;
            int ak   = (lin & 3) * 4;
            float4 v = *(const float4*)&A[(size_t)(m0 + arow) * K + k0 + ak];
            int base = arow * APAD + ak;
            float f[4] = {v.x, v.y, v.z, v.w};
#pragma unroll
            for (int e = 0; e < 4; e++) {
                uint32_t big = f2tf32(f[e]);
                As[0][base + e] = big;
                As[1][base + e] = f2tf32(f[e] - __uint_as_float(big));
            }
        }
        // ---- load + split B tile (16x128) ----
#pragma unroll
        for (int q = 0; q < 2; q++) {
            int lin  = tid * 2 + q;
            int brow = lin >> 5;
            int bn   = (lin & 31) * 4;
            float4 v = *(const float4*)&B_in[(size_t)(k0 + brow) * N + n0 + bn];
            int base = brow * BPAD + bn;
            float f[4] = {v.x, v.y, v.z, v.w};
#pragma unroll
            for (int e = 0; e < 4; e++) {
                uint32_t big = f2tf32(f[e]);
                Bs[0][base + e] = big;
                Bs[1][base + e] = f2tf32(f[e] - __uint_as_float(big));
            }
        }
        __syncthreads();

        // ---- compute: 2 k-steps of 8 ----
#pragma unroll
        for (int kk = 0; kk < TBK; kk += 8) {
            uint32_t ab[4][4], asm_[4][4];
#pragma unroll
            for (int mt = 0; mt < 4; mt++) {
                int i0 = (rA + mt * 16) * APAD + kk + cA;
                int i1 = i0 + 8 * APAD;
                ab[mt][0] = As[0][i0];     ab[mt][1] = As[0][i1];
                ab[mt][2] = As[0][i0 + 4]; ab[mt][3] = As[0][i1 + 4];
                asm_[mt][0] = As[1][i0];     asm_[mt][1] = As[1][i1];
                asm_[mt][2] = As[1][i0 + 4]; asm_[mt][3] = As[1][i1 + 4];
            }
#pragma unroll
            for (int nt = 0; nt < 4; nt++) {
                int bi0 = (kk + rB) * BPAD + cB + nt * 8;
                int bi1 = bi0 + 4 * BPAD;
                uint32_t bb0 = Bs[0][bi0], bb1 = Bs[0][bi1];
                uint32_t bs0 = Bs[1][bi0], bs1 = Bs[1][bi1];
#pragma unroll
                for (int mt = 0; mt < 4; mt++) {
                    mma_tf32(acc[mt][nt], ab[mt],   bb0, bb1);  // big*big
                    mma_tf32(acc[mt][nt], ab[mt],   bs0, bs1);  // big*small
                    mma_tf32(acc[mt][nt], asm_[mt], bb0, bb1);  // small*big
                }
            }
        }
    }

    // ---- epilogue ----
    if (MODE == 0) {
        const int sec   = n0 >> 10;                 // 0=q 1=k 2=v
        float* dst = (sec == 0) ? g_q : (sec == 1) ? g_k : g_v;
#pragma unroll
        for (int mt = 0; mt < 4; mt++) {
#pragma unroll
            for (int nt = 0; nt < 4; nt++) {
                int r  = m0 + wm * 64 + mt * 16 + (lane >> 2);
                int cc = n0 + wn * 32 + nt * 8 + 2 * (lane & 3);
                int c10 = cc & 1023;
                int h   = c10 >> 6;
                int d0  = c10 & 63;
                int b   = r >> 11;
                int s   = r & 2047;
                size_t base = (((size_t)(b * HH + h)) * SS + s) * DD + d0;
                *(float2*)&dst[base] =
                    make_float2(acc[mt][nt][0], acc[mt][nt][1]);
                *(float2*)&dst[base + 8 * DD] =
                    make_float2(acc[mt][nt][2], acc[mt][nt][3]);
            }
        }
    } else {
#pragma unroll
        for (int mt = 0; mt < 4; mt++) {
#pragma unroll
            for (int nt = 0; nt < 4; nt++) {
                int r  = m0 + wm * 64 + mt * 16 + (lane >> 2);
                int cc = n0 + wn * 32 + nt * 8 + 2 * (lane & 3);
                size_t i0 = (size_t)r * N + cc;
                *(float2*)&C[i0] =
                    make_float2(acc[mt][nt][0], acc[mt][nt][1]);
                *(float2*)&C[i0 + (size_t)8 * N] =
                    make_float2(acc[mt][nt][2], acc[mt][nt][3]);
            }
        }
    }
}

// ---------------------------------------------------------------------------
// Flash attention (unchanged from R1): 64-query tile, online softmax, causal.
// ---------------------------------------------------------------------------
#define FP 68
#define FLASH_SMEM (4 * 64 * FP * 4)

__global__ __launch_bounds__(256) void flash_kernel(float* __restrict__ gout)
{
    const int qt = blockIdx.x;
    const int bh = blockIdx.y;
    const int q0 = qt * 64;
    const float* qb = g_q + (size_t)bh * SS * DD;
    const float* kb = g_k + (size_t)bh * SS * DD;
    const float* vb = g_v + (size_t)bh * SS * DD;
    const int b = bh >> 4, h = bh & 15;
    float* ob = gout + (size_t)b * SS * EE + h * DD;

    extern __shared__ float sm[];
    float* Qt = sm;
    float* Kt = sm + 64 * FP;
    float* Vs = sm + 2 * 64 * FP;
    float* Ps = sm + 3 * 64 * FP;

    const int tid = threadIdx.x;
    const int tx = tid & 15;
    const int ty = tid >> 4;

#pragma unroll
    for (int u = 0; u < 16; u++) {
        int lin = u * 256 + tid;
        int r = lin >> 6, d = lin & 63;
        Qt[d * FP + r] = qb[(size_t)(q0 + r) * DD + d];
    }

    float acc[4][4];
#pragma unroll
    for (int i = 0; i < 4; i++)
#pragma unroll
        for (int j = 0; j < 4; j++) acc[i][j] = 0.0f;
    float m_i[4] = {-1e30f, -1e30f, -1e30f, -1e30f};
    float l_i[4] = {0.0f, 0.0f, 0.0f, 0.0f};
    const float scale = 0.125f;

    for (int jt = 0; jt <= qt; jt++) {
        __syncthreads();
        const int k0 = jt * 64;
#pragma unroll
        for (int u = 0; u < 16; u++) {
            int lin = u * 256 + tid;
            int c = lin >> 6, d = lin & 63;
            size_t gidx = (size_t)(k0 + c) * DD + d;
            Kt[d * FP + c] = kb[gidx];
            Vs[c * FP + d] = vb[gidx];
        }
        __syncthreads();

        float s[4][4];
#pragma unroll
        for (int i = 0; i < 4; i++)
#pragma unroll
            for (int j = 0; j < 4; j++) s[i][j] = 0.0f;
#pragma unroll 8
        for (int d = 0; d < 64; d++) {
            float4 av = *(float4*)&Qt[d * FP + ty * 4];
            float4 bv = *(float4*)&Kt[d * FP + tx * 4];
            float a[4] = {av.x, av.y, av.z, av.w};
            float bb2[4] = {bv.x, bv.y, bv.z, bv.w};
#pragma unroll
            for (int i = 0; i < 4; i++)
#pragma unroll
                for (int j = 0; j < 4; j++) s[i][j] += a[i] * bb2[j];
        }

        const bool diag = (jt == qt);
#pragma unroll
        for (int i = 0; i < 4; i++) {
            int r = ty * 4 + i;
#pragma unroll
            for (int j = 0; j < 4; j++) {
                float v = s[i][j] * scale;
                if (diag && (tx * 4 + j) > r) v = -1e30f;
                s[i][j] = v;
            }
        }

#pragma unroll
        for (int i = 0; i < 4; i++) {
            float mx = fmaxf(fmaxf(s[i][0], s[i][1]), fmaxf(s[i][2], s[i][3]));
            mx = fmaxf(mx, __shfl_xor_sync(0xffffffffu, mx, 1));
            mx = fmaxf(mx, __shfl_xor_sync(0xffffffffu, mx, 2));
            mx = fmaxf(mx, __shfl_xor_sync(0xffffffffu, mx, 4));
            mx = fmaxf(mx, __shfl_xor_sync(0xffffffffu, mx, 8));
            float mnew = fmaxf(m_i[i], mx);
            float corr = __expf(m_i[i] - mnew);
            m_i[i] = mnew;
            float rs = 0.0f;
#pragma unroll
            for (int j = 0; j < 4; j++) {
                float p = __expf(s[i][j] - mnew);
                s[i][j] = p;
                rs += p;
            }
            rs += __shfl_xor_sync(0xffffffffu, rs, 1);
            rs += __shfl_xor_sync(0xffffffffu, rs, 2);
            rs += __shfl_xor_sync(0xffffffffu, rs, 4);
            rs += __shfl_xor_sync(0xffffffffu, rs, 8);
            l_i[i] = l_i[i] * corr + rs;
#pragma unroll
            for (int j = 0; j < 4; j++) acc[i][j] *= corr;
            *(float4*)&Ps[(ty * 4 + i) * FP + tx * 4] =
                make_float4(s[i][0], s[i][1], s[i][2], s[i][3]);
        }
        __syncthreads();

#pragma unroll 8
        for (int kk = 0; kk < 64; kk++) {
            float4 vv = *(float4*)&Vs[kk * FP + tx * 4];
            float vj[4] = {vv.x, vv.y, vv.z, vv.w};
#pragma unroll
            for (int i = 0; i < 4; i++) {
                float p = Ps[(ty * 4 + i) * FP + kk];
#pragma unroll
                for (int j = 0; j < 4; j++) acc[i][j] += p * vj[j];
            }
        }
    }

#pragma unroll
    for (int i = 0; i < 4; i++) {
        float inv = 1.0f / l_i[i];
        int sgl = q0 + ty * 4 + i;
        *(float4*)&ob[(size_t)sgl * EE + tx * 4] =
            make_float4(acc[i][0] * inv, acc[i][1] * inv,
                        acc[i][2] * inv, acc[i][3] * inv);
    }
}

// ---------------------------------------------------------------------------
extern "C" void kernel_launch(void* const* d_in, const int* in_sizes, int n_in,
                              void* d_out, int out_size)
{
    const float* x      = (const float*)d_in[0];
    const float* w_attn = (const float*)d_in[1];
    const float* w_proj = (const float*)d_in[2];
    float* out = (float*)d_out;

    // 1. QKV GEMM (3xTF32 tensor cores) -> g_q/g_k/g_v
    {
        dim3 grid(3 * EE / TBN, M_TOT / TBM);     // (24, 64)
        tf32_gemm<0><<<grid, 256>>>(x, w_attn, nullptr, M_TOT, 3 * EE, EE);
    }

    // 2. Flash attention -> g_y
    {
        cudaFuncSetAttribute(flash_kernel,
                             cudaFuncAttributeMaxDynamicSharedMemorySize,
                             FLASH_SMEM);
        float* gy_ptr = nullptr;
        cudaGetSymbolAddress((void**)&gy_ptr, g_y);
        dim3 grid(SS / 64, BB * HH);              // (32, 64)
        flash_kernel<<<grid, 256, FLASH_SMEM>>>(gy_ptr);
    }

    // 3. Proj GEMM (3xTF32 tensor cores): g_y @ w_proj -> out
    {
        dim3 grid(EE / TBN, M_TOT / TBM);         // (8, 64)
        tf32_gemm<1><<<grid, 256>>>(nullptr, w_proj, out, M_TOT, EE, EE);
    }
}

// round 4
// speedup vs baseline: 2.5344x; 2.5146x over previous
#include <cuda_runtime.h>
#include <cuda_bf16.h>
#include <cstdint>

#define BB 4
#define SS 2048
#define EE 1024
#define HH 16
#define DD 64
#define M_TOT (BB * SS)     // 8192
#define KDIM EE             // GEMM K = 1024

// bf16 split operands (no fp32 intermediates anywhere)
__device__ __nv_bfloat16 g_xb[M_TOT * EE],   g_xs[M_TOT * EE];
__device__ __nv_bfloat16 g_wab[3 * EE * EE], g_was[3 * EE * EE];  // [N=3E][K]
__device__ __nv_bfloat16 g_wpb[EE * EE],     g_wps[EE * EE];      // [N=E][K]
__device__ __nv_bfloat16 g_qb[BB * HH * SS * DD], g_qs[BB * HH * SS * DD]; // [b,h,s,d]
__device__ __nv_bfloat16 g_kb[BB * HH * SS * DD], g_ks[BB * HH * SS * DD]; // [b,h,s,d]
__device__ __nv_bfloat16 g_vb[BB * HH * SS * DD], g_vs[BB * HH * SS * DD]; // [b,h,d,s] (transposed)
__device__ __nv_bfloat16 g_yb[M_TOT * EE],   g_ys[M_TOT * EE];    // [M][E]

// ---------------------------------------------------------------------------
// Helpers
// ---------------------------------------------------------------------------
__device__ __forceinline__ uint32_t sm2u32(const void* p) {
    uint32_t a;
    asm("{ .reg .u64 t; cvta.to.shared.u64 t, %1; cvt.u32.u64 %0, t; }"
        : "=r"(a) : "l"(p));
    return a;
}

__device__ __forceinline__ uint32_t packbf(float lo, float hi) {
    uint32_t r;
    asm("cvt.rn.bf16x2.f32 %0, %1, %2;" : "=r"(r) : "f"(hi), "f"(lo));
    return r;
}

__device__ __forceinline__ void mma_bf16(float* c, const uint32_t* a,
                                         uint32_t b0, uint32_t b1) {
    asm volatile(
        "mma.sync.aligned.m16n8k16.row.col.f32.bf16.bf16.f32 "
        "{%0,%1,%2,%3}, {%4,%5,%6,%7}, {%8,%9}, {%0,%1,%2,%3};\n"
        : "+f"(c[0]), "+f"(c[1]), "+f"(c[2]), "+f"(c[3])
        : "r"(a[0]), "r"(a[1]), "r"(a[2]), "r"(a[3]), "r"(b0), "r"(b1));
}

#define CP16(dst, src) \
    asm volatile("cp.async.cg.shared.global [%0], [%1], 16;" :: "r"(dst), "l"(src))
#define CP_COMMIT() asm volatile("cp.async.commit_group;")

// ---------------------------------------------------------------------------
// Prep kernels
// ---------------------------------------------------------------------------
__global__ void split_kernel(const float* __restrict__ in,
                             __nv_bfloat16* __restrict__ ob,
                             __nv_bfloat16* __restrict__ os, int n4)
{
    int i = blockIdx.x * blockDim.x + threadIdx.x;
    if (i >= n4) return;
    float4 v = ((const float4*)in)[i];
    float f[4] = {v.x, v.y, v.z, v.w};
    uint2 pb, ps;
    __nv_bfloat16* bb = (__nv_bfloat16*)&pb;
    __nv_bfloat16* ss = (__nv_bfloat16*)&ps;
#pragma unroll
    for (int e = 0; e < 4; e++) {
        __nv_bfloat16 b = __float2bfloat16(f[e]);
        bb[e] = b;
        ss[e] = __float2bfloat16(f[e] - __bfloat162float(b));
    }
    ((uint2*)ob)[i] = pb;
    ((uint2*)os)[i] = ps;
}

// w[K,N] fp32 -> out[N,K] bf16 big/small. Block 32x8, tile 32x32.
__global__ void transpose_split_kernel(const float* __restrict__ w,
                                       __nv_bfloat16* __restrict__ ob,
                                       __nv_bfloat16* __restrict__ os,
                                       int K, int N)
{
    __shared__ float t[32][33];
    int n0 = blockIdx.x * 32, k0 = blockIdx.y * 32;
    int tx = threadIdx.x, ty = threadIdx.y;
#pragma unroll
    for (int i = 0; i < 4; i++)
        t[ty + i * 8][tx] = w[(size_t)(k0 + ty + i * 8) * N + n0 + tx];
    __syncthreads();
#pragma unroll
    for (int i = 0; i < 4; i++) {
        int n = ty + i * 8;
        float f = t[tx][n];
        __nv_bfloat16 b = __float2bfloat16(f);
        size_t idx = (size_t)(n0 + n) * K + k0 + tx;
        ob[idx] = b;
        os[idx] = __float2bfloat16(f - __bfloat162float(b));
    }
}

// ---------------------------------------------------------------------------
// bf16 3-split mma.sync GEMM: C[M,N] = A[M,K] @ Bt[N,K]^T
// Block 128x128, KT=32, cp.async double buffer. 8 warps, warp tile 64x32.
// MODE 0: epilogue -> bf16 split q/k [b,h,s,d] and v [b,h,d,s]
// MODE 1: epilogue -> fp32 C row-major
// ---------------------------------------------------------------------------
#define GKT 32
#define NKT (KDIM / GKT)          // 32
#define AROW_W 20                 // 16 data words + 4 pad (bank-safe)
#define ARR_W (128 * AROW_W)      // 2560 words per array
#define STAGE_W (4 * ARR_W)       // Ab,As,Bb,Bs
#define GEMM_DSMEM (2 * STAGE_W * 4)   // 81920 B

template <int MODE>
__global__ __launch_bounds__(256, 2) void bf_gemm(
    const __nv_bfloat16* __restrict__ Ab, const __nv_bfloat16* __restrict__ As_,
    const __nv_bfloat16* __restrict__ Btb, const __nv_bfloat16* __restrict__ Bts,
    float* __restrict__ C, int Ncols)
{
    extern __shared__ uint32_t sw[];
    const uint32_t sbase = sm2u32(sw);

    const int tid  = threadIdx.x;
    const int lane = tid & 31;
    const int g    = lane >> 2;    // 0..7
    const int t4   = lane & 3;     // 0..3
    const int warp = tid >> 5;
    const int wm   = warp & 1;     // 64-row slab
    const int wn   = warp >> 1;    // 32-col slab
    const int m0   = blockIdx.y * 128;
    const int n0   = blockIdx.x * 128;

    const char* srcs[4] = {
        (const char*)(Ab  + (size_t)m0 * KDIM),
        (const char*)(As_ + (size_t)m0 * KDIM),
        (const char*)(Btb + (size_t)n0 * KDIM),
        (const char*)(Bts + (size_t)n0 * KDIM) };

    float acc[4][4][4];
#pragma unroll
    for (int i = 0; i < 4; i++)
#pragma unroll
        for (int j = 0; j < 4; j++)
#pragma unroll
            for (int e = 0; e < 4; e++) acc[i][j][e] = 0.0f;

    // stage loader: 2048 16B chunks (4 arrays x 128 rows x 4 chunks)
    auto load_stage = [&](int s, int kt) {
        const uint32_t stb = sbase + s * STAGE_W * 4;
#pragma unroll
        for (int i = 0; i < 8; i++) {
            int idx   = i * 256 + tid;
            int arr   = idx >> 9;
            int local = idx & 511;
            int row   = local >> 2;
            int ch    = local & 3;
            uint32_t dst = stb + arr * (ARR_W * 4) + row * (AROW_W * 4) + ch * 16;
            const char* src = srcs[arr] + (size_t)row * (KDIM * 2) + kt * (GKT * 2) + ch * 16;
            CP16(dst, src);
        }
        CP_COMMIT();
    };

    load_stage(0, 0);

    for (int kt = 0; kt < NKT; kt++) {
        const int s = kt & 1;
        if (kt + 1 < NKT) {
            load_stage(s ^ 1, kt + 1);
            asm volatile("cp.async.wait_group 1;");
        } else {
            asm volatile("cp.async.wait_group 0;");
        }
        __syncthreads();

        const uint32_t* SA_b = sw + s * STAGE_W;
        const uint32_t* SA_s = SA_b + ARR_W;
        const uint32_t* SB_b = SA_b + 2 * ARR_W;
        const uint32_t* SB_s = SA_b + 3 * ARR_W;

#pragma unroll
        for (int ks = 0; ks < 2; ks++) {
            const int wc = ks * 8 + t4;
            // preload B fragments for all 4 n-tiles
            uint32_t bb0[4], bb1[4], bs0[4], bs1[4];
#pragma unroll
            for (int nt = 0; nt < 4; nt++) {
                int r = (wn * 32 + nt * 8 + g) * AROW_W;
                bb0[nt] = SB_b[r + wc];
                bb1[nt] = SB_b[r + wc + 4];
                bs0[nt] = SB_s[r + wc];
                bs1[nt] = SB_s[r + wc + 4];
            }
#pragma unroll
            for (int mt = 0; mt < 4; mt++) {
                int r0 = (wm * 64 + mt * 16 + g) * AROW_W;
                int r1 = r0 + 8 * AROW_W;
                uint32_t ab[4], asf[4];
                ab[0] = SA_b[r0 + wc];     ab[1] = SA_b[r1 + wc];
                ab[2] = SA_b[r0 + wc + 4]; ab[3] = SA_b[r1 + wc + 4];
                asf[0] = SA_s[r0 + wc];     asf[1] = SA_s[r1 + wc];
                asf[2] = SA_s[r0 + wc + 4]; asf[3] = SA_s[r1 + wc + 4];
#pragma unroll
                for (int nt = 0; nt < 4; nt++) {
                    mma_bf16(acc[mt][nt], ab,  bb0[nt], bb1[nt]);
                    mma_bf16(acc[mt][nt], ab,  bs0[nt], bs1[nt]);
                    mma_bf16(acc[mt][nt], asf, bb0[nt], bb1[nt]);
                }
            }
        }
        __syncthreads();
    }

    // ---- epilogue ----
#pragma unroll
    for (int mt = 0; mt < 4; mt++) {
#pragma unroll
        for (int nt = 0; nt < 4; nt++) {
            const int r  = m0 + wm * 64 + mt * 16 + g;      // global row (and r+8)
            const int cc = n0 + wn * 32 + nt * 8 + 2 * t4;  // global col pair
            if (MODE == 1) {
                size_t i0 = (size_t)r * Ncols + cc;
                *(float2*)&C[i0] = make_float2(acc[mt][nt][0], acc[mt][nt][1]);
                *(float2*)&C[i0 + (size_t)8 * Ncols] =
                    make_float2(acc[mt][nt][2], acc[mt][nt][3]);
            } else {
                // bf16 big/small split, scatter into q/k ([b,h,s,d]) or v ([b,h,d,s])
                float v0 = acc[mt][nt][0], v1 = acc[mt][nt][1];
                float v2 = acc[mt][nt][2], v3 = acc[mt][nt][3];
                float b0 = __bfloat162float(__float2bfloat16(v0));
                float b1 = __bfloat162float(__float2bfloat16(v1));
                float b2 = __bfloat162float(__float2bfloat16(v2));
                float b3 = __bfloat162float(__float2bfloat16(v3));
                const int sec = cc >> 10;
                const int c10 = cc & 1023;
                const int h   = c10 >> 6;
                const int d0  = c10 & 63;
                const int b   = r >> 11;
                const int sl  = r & 2047;
                if (sec < 2) {
                    __nv_bfloat16* db = (sec == 0) ? g_qb : g_kb;
                    __nv_bfloat16* ds = (sec == 0) ? g_qs : g_ks;
                    size_t i0 = (((size_t)(b * HH + h)) * SS + sl) * DD + d0;
                    *(uint32_t*)&db[i0] = packbf(b0, b1);
                    *(uint32_t*)&ds[i0] = packbf(v0 - b0, v1 - b1);
                    *(uint32_t*)&db[i0 + 8 * DD] = packbf(b2, b3);
                    *(uint32_t*)&ds[i0 + 8 * DD] = packbf(v2 - b2, v3 - b3);
                } else {
                    // transposed store: [b,h,d,s]
                    size_t base = ((size_t)(b * HH + h)) * DD * SS;
                    size_t iA = base + (size_t)d0 * SS + sl;
                    size_t iB = base + (size_t)(d0 + 1) * SS + sl;
                    g_vb[iA]     = __float2bfloat16(b0);
                    g_vs[iA]     = __float2bfloat16(v0 - b0);
                    g_vb[iB]     = __float2bfloat16(b1);
                    g_vs[iB]     = __float2bfloat16(v1 - b1);
                    g_vb[iA + 8] = __float2bfloat16(b2);
                    g_vs[iA + 8] = __float2bfloat16(v2 - b2);
                    g_vb[iB + 8] = __float2bfloat16(b3);
                    g_vs[iB + 8] = __float2bfloat16(v3 - b3);
                }
            }
        }
    }
}

// ---------------------------------------------------------------------------
// Tensor-core flash attention, causal. Block = 128 queries of one (b,h),
// 256 threads / 8 warps, each warp owns 16 query rows. K tiles of 64 keys.
// QK^T: 3-split bf16 mma. Softmax fp32 in C-fragments. P register-resident.
// PV: 3-split bf16 mma. Epilogue writes bf16-split y directly.
// ---------------------------------------------------------------------------
#define FROW_W 36                       // 32 data words + 4 pad
#define FQ_W  (128 * FROW_W)            // Q array words
#define FK_W  (64 * FROW_W)
// layout (words): Qb | Qs | Kb | Ks | Vb | Vs
#define FLASH_W  (2 * FQ_W + 4 * FK_W)
#define FLASH_SMEM (FLASH_W * 4)        // 73728 B

__global__ __launch_bounds__(256, 1) void flash_tc(void)
{
    extern __shared__ uint32_t fw[];
    const uint32_t sbase = sm2u32(fw);

    const int tid  = threadIdx.x;
    const int lane = tid & 31;
    const int g    = lane >> 2;
    const int t4   = lane & 3;
    const int w    = tid >> 5;
    const int qt   = blockIdx.x;        // 0..15
    const int bh   = blockIdx.y;        // 0..63
    const int q0   = qt * 128;
    const int b    = bh >> 4, h = bh & 15;

    const char* qb_src = (const char*)(g_qb + ((size_t)bh * SS + q0) * DD);
    const char* qs_src = (const char*)(g_qs + ((size_t)bh * SS + q0) * DD);

    uint32_t* SQb = fw;
    uint32_t* SQs = fw + FQ_W;
    uint32_t* SKb = fw + 2 * FQ_W;
    uint32_t* SKs = SKb + FK_W;
    uint32_t* SVb = SKb + 2 * FK_W;
    uint32_t* SVs = SKb + 3 * FK_W;
    const uint32_t oQb = 0, oQs = FQ_W * 4, oKb = 2 * FQ_W * 4;
    const uint32_t oKs = oKb + FK_W * 4, oVb = oKb + 2 * FK_W * 4, oVs = oKb + 3 * FK_W * 4;

    // load Q tile once: 2 arrays x 128 rows x 8 chunks = 2048 chunks
#pragma unroll
    for (int i = 0; i < 8; i++) {
        int idx = i * 256 + tid;
        int arr = idx >> 10;            // 0:big 1:small
        int local = idx & 1023;
        int row = local >> 3;
        int ch  = local & 7;
        uint32_t dst = sbase + (arr ? oQs : oQb) + row * (FROW_W * 4) + ch * 16;
        const char* src = (arr ? qs_src : qb_src) + (size_t)row * (DD * 2) + ch * 16;
        CP16(dst, src);
    }
    CP_COMMIT();

    float s4[8][4], y[8][4];
#pragma unroll
    for (int j = 0; j < 8; j++)
#pragma unroll
        for (int e = 0; e < 4; e++) y[j][e] = 0.0f;
    float m0 = -1e30f, m1 = -1e30f, l0 = 0.0f, l1 = 0.0f;

    const int qrow0 = q0 + 16 * w + g;       // this lane's row (and +8)
    const int jmax  = 2 * qt + 2;

    for (int jt = 0; jt < jmax; jt++) {
        const int k0 = jt * 64;
        __syncthreads();   // previous iteration's reads done before overwrite
        // load K (b,s) [key][d] and V (b,s) [d][key] tiles: 4 arrays x 512 chunks
        {
            const char* kb_src = (const char*)(g_kb + ((size_t)bh * SS + k0) * DD);
            const char* ks_src = (const char*)(g_ks + ((size_t)bh * SS + k0) * DD);
            const char* vb_src = (const char*)(g_vb + (size_t)bh * DD * SS) + k0 * 2;
            const char* vs_src = (const char*)(g_vs + (size_t)bh * DD * SS) + k0 * 2;
#pragma unroll
            for (int i = 0; i < 8; i++) {
                int idx = i * 256 + tid;
                int arr = idx >> 9;          // 0:Kb 1:Ks 2:Vb 3:Vs
                int local = idx & 511;
                int row = local >> 3;
                int ch  = local & 7;
                uint32_t off = (arr == 0) ? oKb : (arr == 1) ? oKs : (arr == 2) ? oVb : oVs;
                uint32_t dst = sbase + off + row * (FROW_W * 4) + ch * 16;
                const char* src;
                if (arr == 0)      src = kb_src + (size_t)row * (DD * 2) + ch * 16;
                else if (arr == 1) src = ks_src + (size_t)row * (DD * 2) + ch * 16;
                else if (arr == 2) src = vb_src + (size_t)row * (SS * 2) + ch * 16;
                else               src = vs_src + (size_t)row * (SS * 2) + ch * 16;
                CP16(dst, src);
            }
            CP_COMMIT();
            asm volatile("cp.async.wait_group 0;");
        }
        __syncthreads();

        // warp-level skip: this warp's rows all < k0 -> tile fully masked
        if (k0 > q0 + 16 * w + 15) continue;

        // ---- S = Q K^T (3-split) ----
#pragma unroll
        for (int j = 0; j < 8; j++)
#pragma unroll
            for (int e = 0; e < 4; e++) s4[j][e] = 0.0f;

#pragma unroll
        for (int ks = 0; ks < 4; ks++) {
            const int wc = ks * 8 + t4;
            int r0 = (16 * w + g) * FROW_W;
            int r1 = r0 + 8 * FROW_W;
            uint32_t ab[4], asf[4];
            ab[0] = SQb[r0 + wc];     ab[1] = SQb[r1 + wc];
            ab[2] = SQb[r0 + wc + 4]; ab[3] = SQb[r1 + wc + 4];
            asf[0] = SQs[r0 + wc];     asf[1] = SQs[r1 + wc];
            asf[2] = SQs[r0 + wc + 4]; asf[3] = SQs[r1 + wc + 4];
#pragma unroll
            for (int nt = 0; nt < 8; nt++) {
                int kr = (nt * 8 + g) * FROW_W;
                uint32_t bb0 = SKb[kr + wc], bb1 = SKb[kr + wc + 4];
                uint32_t bs0 = SKs[kr + wc], bs1 = SKs[kr + wc + 4];
                mma_bf16(s4[nt], ab,  bb0, bb1);
                mma_bf16(s4[nt], ab,  bs0, bs1);
                mma_bf16(s4[nt], asf, bb0, bb1);
            }
        }

        // ---- scale + causal mask ----
#pragma unroll
        for (int j = 0; j < 8; j++)
#pragma unroll
            for (int e = 0; e < 4; e++) s4[j][e] *= 0.125f;
        if (k0 + 63 > q0 + 16 * w) {
#pragma unroll
            for (int nt = 0; nt < 8; nt++) {
                int kg = k0 + nt * 8 + 2 * t4;
#pragma unroll
                for (int e = 0; e < 4; e++) {
                    int kk = kg + (e & 1);
                    int qq = qrow0 + ((e >> 1) << 3);
                    if (kk > qq) s4[nt][e] = -1e30f;
                }
            }
        }

        // ---- online softmax (rows r0, r0+8) ----
        float mx0 = -1e30f, mx1 = -1e30f;
#pragma unroll
        for (int j = 0; j < 8; j++) {
            mx0 = fmaxf(mx0, fmaxf(s4[j][0], s4[j][1]));
            mx1 = fmaxf(mx1, fmaxf(s4[j][2], s4[j][3]));
        }
        mx0 = fmaxf(mx0, __shfl_xor_sync(0xffffffffu, mx0, 1));
        mx0 = fmaxf(mx0, __shfl_xor_sync(0xffffffffu, mx0, 2));
        mx1 = fmaxf(mx1, __shfl_xor_sync(0xffffffffu, mx1, 1));
        mx1 = fmaxf(mx1, __shfl_xor_sync(0xffffffffu, mx1, 2));
        float mn0 = fmaxf(m0, mx0), mn1 = fmaxf(m1, mx1);
        float c0 = __expf(m0 - mn0), c1 = __expf(m1 - mn1);
        m0 = mn0; m1 = mn1;
        float sum0 = 0.0f, sum1 = 0.0f;
#pragma unroll
        for (int j = 0; j < 8; j++) {
            s4[j][0] = __expf(s4[j][0] - mn0); sum0 += s4[j][0];
            s4[j][1] = __expf(s4[j][1] - mn0); sum0 += s4[j][1];
            s4[j][2] = __expf(s4[j][2] - mn1); sum1 += s4[j][2];
            s4[j][3] = __expf(s4[j][3] - mn1); sum1 += s4[j][3];
        }
        sum0 += __shfl_xor_sync(0xffffffffu, sum0, 1);
        sum0 += __shfl_xor_sync(0xffffffffu, sum0, 2);
        sum1 += __shfl_xor_sync(0xffffffffu, sum1, 1);
        sum1 += __shfl_xor_sync(0xffffffffu, sum1, 2);
        l0 = l0 * c0 + sum0;
        l1 = l1 * c1 + sum1;
#pragma unroll
        for (int j = 0; j < 8; j++) {
            y[j][0] *= c0; y[j][1] *= c0;
            y[j][2] *= c1; y[j][3] *= c1;
        }

        // ---- Y += P V (3-split, P register-resident) ----
#pragma unroll
        for (int T = 0; T < 4; T++) {
            float p00 = s4[2 * T][0],     p01 = s4[2 * T][1];
            float p10 = s4[2 * T][2],     p11 = s4[2 * T][3];
            float p20 = s4[2 * T + 1][0], p21 = s4[2 * T + 1][1];
            float p30 = s4[2 * T + 1][2], p31 = s4[2 * T + 1][3];
            float b00 = __bfloat162float(__float2bfloat16(p00));
            float b01 = __bfloat162float(__float2bfloat16(p01));
            float b10 = __bfloat162float(__float2bfloat16(p10));
            float b11 = __bfloat162float(__float2bfloat16(p11));
            float b20 = __bfloat162float(__float2bfloat16(p20));
            float b21 = __bfloat162float(__float2bfloat16(p21));
            float b30 = __bfloat162float(__float2bfloat16(p30));
            float b31 = __bfloat162float(__float2bfloat16(p31));
            uint32_t pab[4] = { packbf(b00, b01), packbf(b10, b11),
                                packbf(b20, b21), packbf(b30, b31) };
            uint32_t pas[4] = { packbf(p00 - b00, p01 - b01),
                                packbf(p10 - b10, p11 - b11),
                                packbf(p20 - b20, p21 - b21),
                                packbf(p30 - b30, p31 - b31) };
            const int wc = T * 8 + t4;
#pragma unroll
            for (int nd = 0; nd < 8; nd++) {
                int vr = (nd * 8 + g) * FROW_W;
                uint32_t vb0 = SVb[vr + wc], vb1 = SVb[vr + wc + 4];
                uint32_t vs0 = SVs[vr + wc], vs1 = SVs[vr + wc + 4];
                mma_bf16(y[nd], pab, vb0, vb1);
                mma_bf16(y[nd], pab, vs0, vs1);
                mma_bf16(y[nd], pas, vb0, vb1);
            }
        }
    }

    // ---- normalize + write bf16-split y (row = b*S + s, col = h*64 + d) ----
    float inv0 = 1.0f / l0, inv1 = 1.0f / l1;
    const size_t row0 = (size_t)b * SS + q0 + 16 * w + g;
    const size_t row1 = row0 + 8;
#pragma unroll
    for (int nd = 0; nd < 8; nd++) {
        int col = h * 64 + nd * 8 + 2 * t4;
        float v0 = y[nd][0] * inv0, v1 = y[nd][1] * inv0;
        float v2 = y[nd][2] * inv1, v3 = y[nd][3] * inv1;
        float b0 = __bfloat162float(__float2bfloat16(v0));
        float b1 = __bfloat162float(__float2bfloat16(v1));
        float b2 = __bfloat162float(__float2bfloat16(v2));
        float b3 = __bfloat162float(__float2bfloat16(v3));
        size_t i0 = row0 * EE + col, i1 = row1 * EE + col;
        *(uint32_t*)&g_yb[i0] = packbf(b0, b1);
        *(uint32_t*)&g_ys[i0] = packbf(v0 - b0, v1 - b1);
        *(uint32_t*)&g_yb[i1] = packbf(b2, b3);
        *(uint32_t*)&g_ys[i1] = packbf(v2 - b2, v3 - b3);
    }
}

// ---------------------------------------------------------------------------
extern "C" void kernel_launch(void* const* d_in, const int* in_sizes, int n_in,
                              void* d_out, int out_size)
{
    const float* x      = (const float*)d_in[0];
    const float* w_attn = (const float*)d_in[1];
    const float* w_proj = (const float*)d_in[2];
    float* out = (float*)d_out;

    __nv_bfloat16 *xb, *xs, *wab, *was, *wpb, *wps, *yb, *ys;
    cudaGetSymbolAddress((void**)&xb,  g_xb);
    cudaGetSymbolAddress((void**)&xs,  g_xs);
    cudaGetSymbolAddress((void**)&wab, g_wab);
    cudaGetSymbolAddress((void**)&was, g_was);
    cudaGetSymbolAddress((void**)&wpb, g_wpb);
    cudaGetSymbolAddress((void**)&wps, g_wps);
    cudaGetSymbolAddress((void**)&yb,  g_yb);
    cudaGetSymbolAddress((void**)&ys,  g_ys);

    cudaFuncSetAttribute(bf_gemm<0>, cudaFuncAttributeMaxDynamicSharedMemorySize, GEMM_DSMEM);
    cudaFuncSetAttribute(bf_gemm<1>, cudaFuncAttributeMaxDynamicSharedMemorySize, GEMM_DSMEM);
    cudaFuncSetAttribute(flash_tc,   cudaFuncAttributeMaxDynamicSharedMemorySize, FLASH_SMEM);

    // 0. split x; transpose+split weights
    {
        int n4 = M_TOT * EE / 4;
        split_kernel<<<(n4 + 255) / 256, 256>>>(x, xb, xs, n4);
        dim3 tb(32, 8);
        transpose_split_kernel<<<dim3(3 * EE / 32, EE / 32), tb>>>(w_attn, wab, was, EE, 3 * EE);
        transpose_split_kernel<<<dim3(EE / 32, EE / 32), tb>>>(w_proj, wpb, wps, EE, EE);
    }

    // 1. QKV GEMM -> bf16-split q/k/v (v transposed)
    {
        dim3 grid(3 * EE / 128, M_TOT / 128);   // (24, 64)
        bf_gemm<0><<<grid, 256, GEMM_DSMEM>>>(xb, xs, wab, was, nullptr, 3 * EE);
    }

    // 2. flash attention -> bf16-split y
    {
        dim3 grid(SS / 128, BB * HH);           // (16, 64)
        flash_tc<<<grid, 256, FLASH_SMEM>>>();
    }

    // 3. proj GEMM -> out (fp32)
    {
        dim3 grid(EE / 128, M_TOT / 128);       // (8, 64)
        bf_gemm<1><<<grid, 256, GEMM_DSMEM>>>(yb, ys, wpb, wps, out, EE);
    }
}

// round 5
// speedup vs baseline: 3.2586x; 1.2857x over previous
#include <cuda_runtime.h>
#include <cuda_bf16.h>
#include <cstdint>

#define BB 4
#define SS 2048
#define EE 1024
#define HH 16
#define DD 64
#define M_TOT (BB * SS)     // 8192
#define KDIM EE             // GEMM K = 1024

// bf16 split operands
__device__ __nv_bfloat16 g_xb[M_TOT * EE],   g_xs[M_TOT * EE];
__device__ __nv_bfloat16 g_wab[3 * EE * EE], g_was[3 * EE * EE];  // [N=3E][K]
__device__ __nv_bfloat16 g_wpb[EE * EE],     g_wps[EE * EE];      // [N=E][K]
__device__ __nv_bfloat16 g_qb[BB * HH * SS * DD], g_qs[BB * HH * SS * DD]; // [b,h,s,d]
__device__ __nv_bfloat16 g_kb[BB * HH * SS * DD], g_ks[BB * HH * SS * DD]; // [b,h,s,d]
__device__ __nv_bfloat16 g_vb[BB * HH * SS * DD], g_vs[BB * HH * SS * DD]; // [b,h,d,s]
__device__ __nv_bfloat16 g_yb[M_TOT * EE],   g_ys[M_TOT * EE];    // [M][E]

// ---------------------------------------------------------------------------
// Helpers
// ---------------------------------------------------------------------------
__device__ __forceinline__ uint32_t sm2u32(const void* p) {
    uint32_t a;
    asm("{ .reg .u64 t; cvta.to.shared.u64 t, %1; cvt.u32.u64 %0, t; }"
        : "=r"(a) : "l"(p));
    return a;
}

__device__ __forceinline__ uint32_t packbf(float lo, float hi) {
    uint32_t r;
    asm("cvt.rn.bf16x2.f32 %0, %1, %2;" : "=r"(r) : "f"(hi), "f"(lo));
    return r;
}

__device__ __forceinline__ void mma_bf16(float* c, const uint32_t* a,
                                         uint32_t b0, uint32_t b1) {
    asm volatile(
        "mma.sync.aligned.m16n8k16.row.col.f32.bf16.bf16.f32 "
        "{%0,%1,%2,%3}, {%4,%5,%6,%7}, {%8,%9}, {%0,%1,%2,%3};\n"
        : "+f"(c[0]), "+f"(c[1]), "+f"(c[2]), "+f"(c[3])
        : "r"(a[0]), "r"(a[1]), "r"(a[2]), "r"(a[3]), "r"(b0), "r"(b1));
}

__device__ __forceinline__ void ldm4(uint32_t addr, uint32_t* r) {
    asm volatile("ldmatrix.sync.aligned.m8n8.x4.shared.b16 {%0,%1,%2,%3}, [%4];"
                 : "=r"(r[0]), "=r"(r[1]), "=r"(r[2]), "=r"(r[3]) : "r"(addr));
}

#define CP16(dst, src) \
    asm volatile("cp.async.cg.shared.global [%0], [%1], 16;" :: "r"(dst), "l"(src))
#define CP_COMMIT() asm volatile("cp.async.commit_group;")

// ---------------------------------------------------------------------------
// Prep kernels
// ---------------------------------------------------------------------------
__global__ void split_kernel(const float* __restrict__ in,
                             __nv_bfloat16* __restrict__ ob,
                             __nv_bfloat16* __restrict__ os, int n4)
{
    int i = blockIdx.x * blockDim.x + threadIdx.x;
    if (i >= n4) return;
    float4 v = ((const float4*)in)[i];
    float f[4] = {v.x, v.y, v.z, v.w};
    uint2 pb, ps;
    __nv_bfloat16* bb = (__nv_bfloat16*)&pb;
    __nv_bfloat16* ss = (__nv_bfloat16*)&ps;
#pragma unroll
    for (int e = 0; e < 4; e++) {
        __nv_bfloat16 b = __float2bfloat16(f[e]);
        bb[e] = b;
        ss[e] = __float2bfloat16(f[e] - __bfloat162float(b));
    }
    ((uint2*)ob)[i] = pb;
    ((uint2*)os)[i] = ps;
}

__global__ void transpose_split_kernel(const float* __restrict__ w,
                                       __nv_bfloat16* __restrict__ ob,
                                       __nv_bfloat16* __restrict__ os,
                                       int K, int N)
{
    __shared__ float t[32][33];
    int n0 = blockIdx.x * 32, k0 = blockIdx.y * 32;
    int tx = threadIdx.x, ty = threadIdx.y;
#pragma unroll
    for (int i = 0; i < 4; i++)
        t[ty + i * 8][tx] = w[(size_t)(k0 + ty + i * 8) * N + n0 + tx];
    __syncthreads();
#pragma unroll
    for (int i = 0; i < 4; i++) {
        int n = ty + i * 8;
        float f = t[tx][n];
        __nv_bfloat16 b = __float2bfloat16(f);
        size_t idx = (size_t)(n0 + n) * K + k0 + tx;
        ob[idx] = b;
        os[idx] = __float2bfloat16(f - __bfloat162float(b));
    }
}

// ---------------------------------------------------------------------------
// bf16 3-split mma.sync GEMM with ldmatrix. Block 128x128, KT=32,
// cp.async double buffer, XOR-swizzled smem (64B rows, no padding).
// ---------------------------------------------------------------------------
#define GKT 32
#define NKT (KDIM / GKT)           // 32
#define GARR_B 8192                // 128 rows * 64 B
#define GSTAGE_B (4 * GARR_B)      // 32768
#define GEMM_DSMEM (2 * GSTAGE_B)  // 65536

template <int MODE>
__global__ __launch_bounds__(256, 2) void bf_gemm(
    const __nv_bfloat16* __restrict__ Ab, const __nv_bfloat16* __restrict__ As_,
    const __nv_bfloat16* __restrict__ Btb, const __nv_bfloat16* __restrict__ Bts,
    float* __restrict__ C, int Ncols)
{
    extern __shared__ uint32_t sw4[];
    const uint32_t sbase = sm2u32(sw4);

    const int tid  = threadIdx.x;
    const int lane = tid & 31;
    const int g    = lane >> 2;
    const int t4   = lane & 3;
    const int m_   = lane >> 3;    // ldmatrix matrix id
    const int j_   = lane & 7;     // ldmatrix row-in-matrix
    const int warp = tid >> 5;
    const int wm   = warp & 1;
    const int wn   = warp >> 1;
    const int m0   = blockIdx.y * 128;
    const int n0   = blockIdx.x * 128;

    const char* srcs[4] = {
        (const char*)(Ab  + (size_t)m0 * KDIM),
        (const char*)(As_ + (size_t)m0 * KDIM),
        (const char*)(Btb + (size_t)n0 * KDIM),
        (const char*)(Bts + (size_t)n0 * KDIM) };

    // ldmatrix row bases (per thread, fixed)
    int arow[4], asw[4];
#pragma unroll
    for (int mt = 0; mt < 4; mt++) {
        arow[mt] = wm * 64 + mt * 16 + ((m_ & 1) << 3) + j_;
        asw[mt]  = (arow[mt] >> 1) & 3;
    }
    int brow[2], bsw[2];
#pragma unroll
    for (int p = 0; p < 2; p++) {
        brow[p] = wn * 32 + p * 16 + ((m_ >> 1) << 3) + j_;
        bsw[p]  = (brow[p] >> 1) & 3;
    }

    float acc[4][4][4];
#pragma unroll
    for (int i = 0; i < 4; i++)
#pragma unroll
        for (int j = 0; j < 4; j++)
#pragma unroll
            for (int e = 0; e < 4; e++) acc[i][j][e] = 0.0f;

    auto load_stage = [&](int s, int kt) {
        const uint32_t stb = sbase + s * GSTAGE_B;
#pragma unroll
        for (int i = 0; i < 8; i++) {
            const int arr = i >> 1;                 // compile-time
            int local = ((i & 1) << 8) + tid;       // 0..511
            int row = local >> 2;
            int c   = local & 3;
            uint32_t dst = stb + arr * GARR_B + row * 64 +
                           ((c ^ ((row >> 1) & 3)) << 4);
            const char* src = srcs[arr] + (size_t)row * (KDIM * 2) + kt * 64 + c * 16;
            CP16(dst, src);
        }
        CP_COMMIT();
    };

    load_stage(0, 0);

    for (int kt = 0; kt < NKT; kt++) {
        const int s = kt & 1;
        if (kt + 1 < NKT) {
            load_stage(s ^ 1, kt + 1);
            asm volatile("cp.async.wait_group 1;");
        } else {
            asm volatile("cp.async.wait_group 0;");
        }
        __syncthreads();

        const uint32_t AbO = sbase + s * GSTAGE_B;
        const uint32_t AsO = AbO + GARR_B;
        const uint32_t BbO = AbO + 2 * GARR_B;
        const uint32_t BsO = AbO + 3 * GARR_B;

#pragma unroll
        for (int ks = 0; ks < 2; ks++) {
            const int cA = ks * 2 + (m_ >> 1);
            const int cB = ks * 2 + (m_ & 1);

            uint32_t bb[4][2], bs[4][2];
#pragma unroll
            for (int p = 0; p < 2; p++) {
                uint32_t off = brow[p] * 64 + ((cB ^ bsw[p]) << 4);
                uint32_t r[4], r2[4];
                ldm4(BbO + off, r);
                ldm4(BsO + off, r2);
                bb[2 * p][0] = r[0];  bb[2 * p][1] = r[1];
                bb[2 * p + 1][0] = r[2]; bb[2 * p + 1][1] = r[3];
                bs[2 * p][0] = r2[0]; bs[2 * p][1] = r2[1];
                bs[2 * p + 1][0] = r2[2]; bs[2 * p + 1][1] = r2[3];
            }
#pragma unroll
            for (int mt = 0; mt < 4; mt++) {
                uint32_t off = arow[mt] * 64 + ((cA ^ asw[mt]) << 4);
                uint32_t ab[4], asf[4];
                ldm4(AbO + off, ab);
                ldm4(AsO + off, asf);
#pragma unroll
                for (int nt = 0; nt < 4; nt++) {
                    mma_bf16(acc[mt][nt], ab,  bb[nt][0], bb[nt][1]);
                    mma_bf16(acc[mt][nt], ab,  bs[nt][0], bs[nt][1]);
                    mma_bf16(acc[mt][nt], asf, bb[nt][0], bb[nt][1]);
                }
            }
        }
        __syncthreads();
    }

    // ---- epilogue ----
#pragma unroll
    for (int mt = 0; mt < 4; mt++) {
#pragma unroll
        for (int nt = 0; nt < 4; nt++) {
            const int r  = m0 + wm * 64 + mt * 16 + g;
            const int cc = n0 + wn * 32 + nt * 8 + 2 * t4;
            if (MODE == 1) {
                size_t i0 = (size_t)r * Ncols + cc;
                *(float2*)&C[i0] = make_float2(acc[mt][nt][0], acc[mt][nt][1]);
                *(float2*)&C[i0 + (size_t)8 * Ncols] =
                    make_float2(acc[mt][nt][2], acc[mt][nt][3]);
            } else {
                float v0 = acc[mt][nt][0], v1 = acc[mt][nt][1];
                float v2 = acc[mt][nt][2], v3 = acc[mt][nt][3];
                float b0 = __bfloat162float(__float2bfloat16(v0));
                float b1 = __bfloat162float(__float2bfloat16(v1));
                float b2 = __bfloat162float(__float2bfloat16(v2));
                float b3 = __bfloat162float(__float2bfloat16(v3));
                const int sec = cc >> 10;
                const int c10 = cc & 1023;
                const int h   = c10 >> 6;
                const int d0  = c10 & 63;
                const int b   = r >> 11;
                const int sl  = r & 2047;
                if (sec < 2) {
                    __nv_bfloat16* db = (sec == 0) ? g_qb : g_kb;
                    __nv_bfloat16* ds = (sec == 0) ? g_qs : g_ks;
                    size_t i0 = (((size_t)(b * HH + h)) * SS + sl) * DD + d0;
                    *(uint32_t*)&db[i0] = packbf(b0, b1);
                    *(uint32_t*)&ds[i0] = packbf(v0 - b0, v1 - b1);
                    *(uint32_t*)&db[i0 + 8 * DD] = packbf(b2, b3);
                    *(uint32_t*)&ds[i0 + 8 * DD] = packbf(v2 - b2, v3 - b3);
                } else {
                    size_t base = ((size_t)(b * HH + h)) * DD * SS;
                    size_t iA = base + (size_t)d0 * SS + sl;
                    size_t iB = base + (size_t)(d0 + 1) * SS + sl;
                    g_vb[iA]     = __float2bfloat16(b0);
                    g_vs[iA]     = __float2bfloat16(v0 - b0);
                    g_vb[iB]     = __float2bfloat16(b1);
                    g_vs[iB]     = __float2bfloat16(v1 - b1);
                    g_vb[iA + 8] = __float2bfloat16(b2);
                    g_vs[iA + 8] = __float2bfloat16(v2 - b2);
                    g_vb[iB + 8] = __float2bfloat16(b3);
                    g_vs[iB + 8] = __float2bfloat16(v3 - b3);
                }
            }
        }
    }
}

// ---------------------------------------------------------------------------
// Tensor-core flash attention with ldmatrix + double-buffered K/V.
// Block = 128 queries of one (b,h), 256 threads / 8 warps (16 q rows each).
// Smem (bytes): Qb[0,16K) Qs[16K,32K) | stage s at 32K+s*32K: Kb,Ks,Vb,Vs 8K each
// Rows are 128B, SW128 swizzle c ^ (row&7).
// ---------------------------------------------------------------------------
#define FQ_B   16384
#define FARR_B 8192
#define FSTAGE_B (4 * FARR_B)              // 32768
#define FLASH_SMEM (2 * FQ_B + 2 * FSTAGE_B)   // 98304

__global__ __launch_bounds__(256, 2) void flash_tc(void)
{
    extern __shared__ uint32_t fw4[];
    const uint32_t sbase = sm2u32(fw4);

    const int tid  = threadIdx.x;
    const int lane = tid & 31;
    const int g    = lane >> 2;
    const int t4   = lane & 3;
    const int m_   = lane >> 3;
    const int j_   = lane & 7;
    const int w    = tid >> 5;
    const int qt   = blockIdx.x;
    const int bh   = blockIdx.y;
    const int q0   = qt * 128;
    const int b    = bh >> 4, h = bh & 15;

    const char* qb_src = (const char*)(g_qb + ((size_t)bh * SS + q0) * DD);
    const char* qs_src = (const char*)(g_qs + ((size_t)bh * SS + q0) * DD);
    const char* kb_base = (const char*)(g_kb + (size_t)bh * SS * DD);
    const char* ks_base = (const char*)(g_ks + (size_t)bh * SS * DD);
    const char* vb_base = (const char*)(g_vb + (size_t)bh * DD * SS);
    const char* vs_base = (const char*)(g_vs + (size_t)bh * DD * SS);

    // ldmatrix row bases
    const int qrow_l = 16 * w + ((m_ & 1) << 3) + j_;   // Q (A operand)
    const int qsw    = qrow_l & 7;
    int krow[4], ksw[4];                                 // K/V (B operand)
#pragma unroll
    for (int p = 0; p < 4; p++) {
        krow[p] = p * 16 + ((m_ >> 1) << 3) + j_;
        ksw[p]  = krow[p] & 7;
    }

    // ---- prologue loads: Q + KV stage 0, one commit group ----
#pragma unroll
    for (int i = 0; i < 8; i++) {
        const int arr = i >> 2;                 // 0:Qb 1:Qs
        int local = ((i & 3) << 8) + tid;       // 0..1023
        int row = local >> 3, c = local & 7;
        uint32_t dst = sbase + arr * FQ_B + row * 128 + ((c ^ (row & 7)) << 4);
        const char* src = (arr ? qs_src : qb_src) + (size_t)row * 128 + c * 16;
        CP16(dst, src);
    }
    {
        const int k0 = 0;
#pragma unroll
        for (int i = 0; i < 8; i++) {
            const int arr = i >> 1;
            int local = ((i & 1) << 8) + tid;   // 0..511
            int row = local >> 3, c = local & 7;
            uint32_t dst = sbase + 2 * FQ_B + arr * FARR_B + row * 128 +
                           ((c ^ (row & 7)) << 4);
            const char* src;
            if (arr == 0)      src = kb_base + ((size_t)(k0 + row)) * 128 + c * 16;
            else if (arr == 1) src = ks_base + ((size_t)(k0 + row)) * 128 + c * 16;
            else if (arr == 2) src = vb_base + (size_t)row * (SS * 2) + k0 * 2 + c * 16;
            else               src = vs_base + (size_t)row * (SS * 2) + k0 * 2 + c * 16;
            CP16(dst, src);
        }
    }
    CP_COMMIT();

    float s4[8][4], y[8][4];
#pragma unroll
    for (int j = 0; j < 8; j++)
#pragma unroll
        for (int e = 0; e < 4; e++) y[j][e] = 0.0f;
    float m0 = -1e30f, m1 = -1e30f, l0 = 0.0f, l1 = 0.0f;

    const int qrow0 = q0 + 16 * w + g;
    const int jmax  = 2 * qt + 2;

    for (int jt = 0; jt < jmax; jt++) {
        const int s  = jt & 1;
        const int k0 = jt * 64;

        // prefetch next stage
        if (jt + 1 < jmax) {
            const int kn = (jt + 1) * 64;
            const uint32_t stb = sbase + 2 * FQ_B + (s ^ 1) * FSTAGE_B;
#pragma unroll
            for (int i = 0; i < 8; i++) {
                const int arr = i >> 1;
                int local = ((i & 1) << 8) + tid;
                int row = local >> 3, c = local & 7;
                uint32_t dst = stb + arr * FARR_B + row * 128 + ((c ^ (row & 7)) << 4);
                const char* src;
                if (arr == 0)      src = kb_base + ((size_t)(kn + row)) * 128 + c * 16;
                else if (arr == 1) src = ks_base + ((size_t)(kn + row)) * 128 + c * 16;
                else if (arr == 2) src = vb_base + (size_t)row * (SS * 2) + kn * 2 + c * 16;
                else               src = vs_base + (size_t)row * (SS * 2) + kn * 2 + c * 16;
                CP16(dst, src);
            }
            CP_COMMIT();
            asm volatile("cp.async.wait_group 1;");
        } else {
            asm volatile("cp.async.wait_group 0;");
        }
        __syncthreads();

        const bool active = (k0 <= q0 + 16 * w + 15);
        if (active) {
            const uint32_t KbO = sbase + 2 * FQ_B + s * FSTAGE_B;
            const uint32_t KsO = KbO + FARR_B;
            const uint32_t VbO = KbO + 2 * FARR_B;
            const uint32_t VsO = KbO + 3 * FARR_B;

            // ---- S = Q K^T (3-split) ----
#pragma unroll
            for (int j = 0; j < 8; j++)
#pragma unroll
                for (int e = 0; e < 4; e++) s4[j][e] = 0.0f;

#pragma unroll
            for (int ks = 0; ks < 4; ks++) {
                const int cA = ks * 2 + (m_ >> 1);
                const int cB = ks * 2 + (m_ & 1);
                uint32_t qoff = qrow_l * 128 + ((cA ^ qsw) << 4);
                uint32_t ab[4], asf[4];
                ldm4(sbase + qoff, ab);
                ldm4(sbase + FQ_B + qoff, asf);
#pragma unroll
                for (int p = 0; p < 4; p++) {
                    uint32_t off = krow[p] * 128 + ((cB ^ ksw[p]) << 4);
                    uint32_t rb[4], rs[4];
                    ldm4(KbO + off, rb);
                    ldm4(KsO + off, rs);
                    mma_bf16(s4[2 * p],     ab,  rb[0], rb[1]);
                    mma_bf16(s4[2 * p],     ab,  rs[0], rs[1]);
                    mma_bf16(s4[2 * p],     asf, rb[0], rb[1]);
                    mma_bf16(s4[2 * p + 1], ab,  rb[2], rb[3]);
                    mma_bf16(s4[2 * p + 1], ab,  rs[2], rs[3]);
                    mma_bf16(s4[2 * p + 1], asf, rb[2], rb[3]);
                }
            }

            // ---- scale + causal mask ----
#pragma unroll
            for (int j = 0; j < 8; j++)
#pragma unroll
                for (int e = 0; e < 4; e++) s4[j][e] *= 0.125f;
            if (k0 + 63 > q0 + 16 * w) {
#pragma unroll
                for (int nt = 0; nt < 8; nt++) {
                    int kg = k0 + nt * 8 + 2 * t4;
#pragma unroll
                    for (int e = 0; e < 4; e++) {
                        int kk = kg + (e & 1);
                        int qq = qrow0 + ((e >> 1) << 3);
                        if (kk > qq) s4[nt][e] = -1e30f;
                    }
                }
            }

            // ---- online softmax ----
            float mx0 = -1e30f, mx1 = -1e30f;
#pragma unroll
            for (int j = 0; j < 8; j++) {
                mx0 = fmaxf(mx0, fmaxf(s4[j][0], s4[j][1]));
                mx1 = fmaxf(mx1, fmaxf(s4[j][2], s4[j][3]));
            }
            mx0 = fmaxf(mx0, __shfl_xor_sync(0xffffffffu, mx0, 1));
            mx0 = fmaxf(mx0, __shfl_xor_sync(0xffffffffu, mx0, 2));
            mx1 = fmaxf(mx1, __shfl_xor_sync(0xffffffffu, mx1, 1));
            mx1 = fmaxf(mx1, __shfl_xor_sync(0xffffffffu, mx1, 2));
            float mn0 = fmaxf(m0, mx0), mn1 = fmaxf(m1, mx1);
            float c0 = __expf(m0 - mn0), c1 = __expf(m1 - mn1);
            m0 = mn0; m1 = mn1;
            float sum0 = 0.0f, sum1 = 0.0f;
#pragma unroll
            for (int j = 0; j < 8; j++) {
                s4[j][0] = __expf(s4[j][0] - mn0); sum0 += s4[j][0];
                s4[j][1] = __expf(s4[j][1] - mn0); sum0 += s4[j][1];
                s4[j][2] = __expf(s4[j][2] - mn1); sum1 += s4[j][2];
                s4[j][3] = __expf(s4[j][3] - mn1); sum1 += s4[j][3];
            }
            sum0 += __shfl_xor_sync(0xffffffffu, sum0, 1);
            sum0 += __shfl_xor_sync(0xffffffffu, sum0, 2);
            sum1 += __shfl_xor_sync(0xffffffffu, sum1, 1);
            sum1 += __shfl_xor_sync(0xffffffffu, sum1, 2);
            l0 = l0 * c0 + sum0;
            l1 = l1 * c1 + sum1;
#pragma unroll
            for (int j = 0; j < 8; j++) {
                y[j][0] *= c0; y[j][1] *= c0;
                y[j][2] *= c1; y[j][3] *= c1;
            }

            // ---- Y += P V (3-split, P register-resident) ----
#pragma unroll
            for (int kk = 0; kk < 4; kk++) {
                float p00 = s4[2 * kk][0],     p01 = s4[2 * kk][1];
                float p10 = s4[2 * kk][2],     p11 = s4[2 * kk][3];
                float p20 = s4[2 * kk + 1][0], p21 = s4[2 * kk + 1][1];
                float p30 = s4[2 * kk + 1][2], p31 = s4[2 * kk + 1][3];
                float b00 = __bfloat162float(__float2bfloat16(p00));
                float b01 = __bfloat162float(__float2bfloat16(p01));
                float b10 = __bfloat162float(__float2bfloat16(p10));
                float b11 = __bfloat162float(__float2bfloat16(p11));
                float b20 = __bfloat162float(__float2bfloat16(p20));
                float b21 = __bfloat162float(__float2bfloat16(p21));
                float b30 = __bfloat162float(__float2bfloat16(p30));
                float b31 = __bfloat162float(__float2bfloat16(p31));
                uint32_t pab[4] = { packbf(b00, b01), packbf(b10, b11),
                                    packbf(b20, b21), packbf(b30, b31) };
                uint32_t pas[4] = { packbf(p00 - b00, p01 - b01),
                                    packbf(p10 - b10, p11 - b11),
                                    packbf(p20 - b20, p21 - b21),
                                    packbf(p30 - b30, p31 - b31) };
                const int cV = kk * 2 + (m_ & 1);
#pragma unroll
                for (int p = 0; p < 4; p++) {
                    uint32_t off = krow[p] * 128 + ((cV ^ ksw[p]) << 4);
                    uint32_t rv[4], rvs[4];
                    ldm4(VbO + off, rv);
                    ldm4(VsO + off, rvs);
                    mma_bf16(y[2 * p],     pab, rv[0],  rv[1]);
                    mma_bf16(y[2 * p],     pab, rvs[0], rvs[1]);
                    mma_bf16(y[2 * p],     pas, rv[0],  rv[1]);
                    mma_bf16(y[2 * p + 1], pab, rv[2],  rv[3]);
                    mma_bf16(y[2 * p + 1], pab, rvs[2], rvs[3]);
                    mma_bf16(y[2 * p + 1], pas, rv[2],  rv[3]);
                }
            }
        }
        __syncthreads();
    }

    // ---- normalize + write bf16-split y ----
    float inv0 = 1.0f / l0, inv1 = 1.0f / l1;
    const size_t row0 = (size_t)b * SS + q0 + 16 * w + g;
    const size_t row1 = row0 + 8;
#pragma unroll
    for (int nd = 0; nd < 8; nd++) {
        int col = h * 64 + nd * 8 + 2 * t4;
        float v0 = y[nd][0] * inv0, v1 = y[nd][1] * inv0;
        float v2 = y[nd][2] * inv1, v3 = y[nd][3] * inv1;
        float b0 = __bfloat162float(__float2bfloat16(v0));
        float b1 = __bfloat162float(__float2bfloat16(v1));
        float b2 = __bfloat162float(__float2bfloat16(v2));
        float b3 = __bfloat162float(__float2bfloat16(v3));
        size_t i0 = row0 * EE + col, i1 = row1 * EE + col;
        *(uint32_t*)&g_yb[i0] = packbf(b0, b1);
        *(uint32_t*)&g_ys[i0] = packbf(v0 - b0, v1 - b1);
        *(uint32_t*)&g_yb[i1] = packbf(b2, b3);
        *(uint32_t*)&g_ys[i1] = packbf(v2 - b2, v3 - b3);
    }
}

// ---------------------------------------------------------------------------
extern "C" void kernel_launch(void* const* d_in, const int* in_sizes, int n_in,
                              void* d_out, int out_size)
{
    const float* x      = (const float*)d_in[0];
    const float* w_attn = (const float*)d_in[1];
    const float* w_proj = (const float*)d_in[2];
    float* out = (float*)d_out;

    __nv_bfloat16 *xb, *xs, *wab, *was, *wpb, *wps, *yb, *ys;
    cudaGetSymbolAddress((void**)&xb,  g_xb);
    cudaGetSymbolAddress((void**)&xs,  g_xs);
    cudaGetSymbolAddress((void**)&wab, g_wab);
    cudaGetSymbolAddress((void**)&was, g_was);
    cudaGetSymbolAddress((void**)&wpb, g_wpb);
    cudaGetSymbolAddress((void**)&wps, g_wps);
    cudaGetSymbolAddress((void**)&yb,  g_yb);
    cudaGetSymbolAddress((void**)&ys,  g_ys);

    cudaFuncSetAttribute(bf_gemm<0>, cudaFuncAttributeMaxDynamicSharedMemorySize, GEMM_DSMEM);
    cudaFuncSetAttribute(bf_gemm<1>, cudaFuncAttributeMaxDynamicSharedMemorySize, GEMM_DSMEM);
    cudaFuncSetAttribute(flash_tc,   cudaFuncAttributeMaxDynamicSharedMemorySize, FLASH_SMEM);

    // 0. split x; transpose+split weights
    {
        int n4 = M_TOT * EE / 4;
        split_kernel<<<(n4 + 255) / 256, 256>>>(x, xb, xs, n4);
        dim3 tb(32, 8);
        transpose_split_kernel<<<dim3(3 * EE / 32, EE / 32), tb>>>(w_attn, wab, was, EE, 3 * EE);
        transpose_split_kernel<<<dim3(EE / 32, EE / 32), tb>>>(w_proj, wpb, wps, EE, EE);
    }

    // 1. QKV GEMM -> bf16-split q/k/v (v transposed)
    {
        dim3 grid(3 * EE / 128, M_TOT / 128);   // (24, 64)
        bf_gemm<0><<<grid, 256, GEMM_DSMEM>>>(xb, xs, wab, was, nullptr, 3 * EE);
    }

    // 2. flash attention -> bf16-split y
    {
        dim3 grid(SS / 128, BB * HH);           // (16, 64)
        flash_tc<<<grid, 256, FLASH_SMEM>>>();
    }

    // 3. proj GEMM -> out (fp32)
    {
        dim3 grid(EE / 128, M_TOT / 128);       // (8, 64)
        bf_gemm<1><<<grid, 256, GEMM_DSMEM>>>(yb, ys, wpb, wps, out, EE);
    }
}

// round 6
// speedup vs baseline: 3.2624x; 1.0012x over previous
#include <cuda_runtime.h>
#include <cuda_bf16.h>
#include <cstdint>

#define BB 4
#define SS 2048
#define EE 1024
#define HH 16
#define DD 64
#define M_TOT (BB * SS)     // 8192
#define KDIM EE             // GEMM K = 1024

// bf16 split operands
__device__ __nv_bfloat16 g_xb[M_TOT * EE],   g_xs[M_TOT * EE];
__device__ __nv_bfloat16 g_wab[3 * EE * EE], g_was[3 * EE * EE];  // [N=3E][K]
__device__ __nv_bfloat16 g_wpb[EE * EE],     g_wps[EE * EE];      // [N=E][K]
__device__ __nv_bfloat16 g_qb[BB * HH * SS * DD], g_qs[BB * HH * SS * DD]; // [b,h,s,d]
__device__ __nv_bfloat16 g_kb[BB * HH * SS * DD], g_ks[BB * HH * SS * DD]; // [b,h,s,d]
__device__ __nv_bfloat16 g_vb[BB * HH * SS * DD], g_vs[BB * HH * SS * DD]; // [b,h,d,s]
__device__ __nv_bfloat16 g_yb[M_TOT * EE],   g_ys[M_TOT * EE];    // [M][E]

// ---------------------------------------------------------------------------
// Helpers
// ---------------------------------------------------------------------------
__device__ __forceinline__ uint32_t sm2u32(const void* p) {
    uint32_t a;
    asm("{ .reg .u64 t; cvta.to.shared.u64 t, %1; cvt.u32.u64 %0, t; }"
        : "=r"(a) : "l"(p));
    return a;
}

__device__ __forceinline__ uint32_t packbf(float lo, float hi) {
    uint32_t r;
    asm("cvt.rn.bf16x2.f32 %0, %1, %2;" : "=r"(r) : "f"(hi), "f"(lo));
    return r;
}

__device__ __forceinline__ void mma_bf16(float* c, const uint32_t* a,
                                         uint32_t b0, uint32_t b1) {
    asm volatile(
        "mma.sync.aligned.m16n8k16.row.col.f32.bf16.bf16.f32 "
        "{%0,%1,%2,%3}, {%4,%5,%6,%7}, {%8,%9}, {%0,%1,%2,%3};\n"
        : "+f"(c[0]), "+f"(c[1]), "+f"(c[2]), "+f"(c[3])
        : "r"(a[0]), "r"(a[1]), "r"(a[2]), "r"(a[3]), "r"(b0), "r"(b1));
}

__device__ __forceinline__ void ldm4(uint32_t addr, uint32_t* r) {
    asm volatile("ldmatrix.sync.aligned.m8n8.x4.shared.b16 {%0,%1,%2,%3}, [%4];"
                 : "=r"(r[0]), "=r"(r[1]), "=r"(r[2]), "=r"(r[3]) : "r"(addr));
}

#define CP16(dst, src) \
    asm volatile("cp.async.cg.shared.global [%0], [%1], 16;" :: "r"(dst), "l"(src))
#define CP_COMMIT() asm volatile("cp.async.commit_group;")

// ---------------------------------------------------------------------------
// Prep kernels
// ---------------------------------------------------------------------------
__global__ void split_kernel(const float* __restrict__ in,
                             __nv_bfloat16* __restrict__ ob,
                             __nv_bfloat16* __restrict__ os, int n4)
{
    int i = blockIdx.x * blockDim.x + threadIdx.x;
    if (i >= n4) return;
    float4 v = ((const float4*)in)[i];
    float f[4] = {v.x, v.y, v.z, v.w};
    uint2 pb, ps;
    __nv_bfloat16* bb = (__nv_bfloat16*)&pb;
    __nv_bfloat16* ss = (__nv_bfloat16*)&ps;
#pragma unroll
    for (int e = 0; e < 4; e++) {
        __nv_bfloat16 b = __float2bfloat16(f[e]);
        bb[e] = b;
        ss[e] = __float2bfloat16(f[e] - __bfloat162float(b));
    }
    ((uint2*)ob)[i] = pb;
    ((uint2*)os)[i] = ps;
}

__global__ void transpose_split_kernel(const float* __restrict__ w,
                                       __nv_bfloat16* __restrict__ ob,
                                       __nv_bfloat16* __restrict__ os,
                                       int K, int N)
{
    __shared__ float t[32][33];
    int n0 = blockIdx.x * 32, k0 = blockIdx.y * 32;
    int tx = threadIdx.x, ty = threadIdx.y;
#pragma unroll
    for (int i = 0; i < 4; i++)
        t[ty + i * 8][tx] = w[(size_t)(k0 + ty + i * 8) * N + n0 + tx];
    __syncthreads();
#pragma unroll
    for (int i = 0; i < 4; i++) {
        int n = ty + i * 8;
        float f = t[tx][n];
        __nv_bfloat16 b = __float2bfloat16(f);
        size_t idx = (size_t)(n0 + n) * K + k0 + tx;
        ob[idx] = b;
        os[idx] = __float2bfloat16(f - __bfloat162float(b));
    }
}

// ---------------------------------------------------------------------------
// bf16 3-split mma.sync GEMM, ldmatrix, 3-stage cp.async pipeline (1 sync/kt).
// Block 128x128, KT=32, XOR-swizzled smem (64B rows).
// ---------------------------------------------------------------------------
#define GKT 32
#define NKT (KDIM / GKT)           // 32
#define GARR_B 8192                // 128 rows * 64 B
#define GSTAGE_B (4 * GARR_B)      // 32768
#define GEMM_DSMEM (3 * GSTAGE_B)  // 98304

template <int MODE>
__global__ __launch_bounds__(256, 2) void bf_gemm(
    const __nv_bfloat16* __restrict__ Ab, const __nv_bfloat16* __restrict__ As_,
    const __nv_bfloat16* __restrict__ Btb, const __nv_bfloat16* __restrict__ Bts,
    float* __restrict__ C, int Ncols)
{
    extern __shared__ uint32_t sw4[];
    const uint32_t sbase = sm2u32(sw4);

    const int tid  = threadIdx.x;
    const int lane = tid & 31;
    const int g    = lane >> 2;
    const int t4   = lane & 3;
    const int m_   = lane >> 3;    // ldmatrix matrix id
    const int j_   = lane & 7;     // ldmatrix row-in-matrix
    const int warp = tid >> 5;
    const int wm   = warp & 1;
    const int wn   = warp >> 1;
    const int m0   = blockIdx.y * 128;
    const int n0   = blockIdx.x * 128;

    const char* srcs[4] = {
        (const char*)(Ab  + (size_t)m0 * KDIM),
        (const char*)(As_ + (size_t)m0 * KDIM),
        (const char*)(Btb + (size_t)n0 * KDIM),
        (const char*)(Bts + (size_t)n0 * KDIM) };

    int arow[4], asw[4];
#pragma unroll
    for (int mt = 0; mt < 4; mt++) {
        arow[mt] = wm * 64 + mt * 16 + ((m_ & 1) << 3) + j_;
        asw[mt]  = (arow[mt] >> 1) & 3;
    }
    int brow[2], bsw[2];
#pragma unroll
    for (int p = 0; p < 2; p++) {
        brow[p] = wn * 32 + p * 16 + ((m_ >> 1) << 3) + j_;
        bsw[p]  = (brow[p] >> 1) & 3;
    }

    float acc[4][4][4];
#pragma unroll
    for (int i = 0; i < 4; i++)
#pragma unroll
        for (int j = 0; j < 4; j++)
#pragma unroll
            for (int e = 0; e < 4; e++) acc[i][j][e] = 0.0f;

    auto load_stage = [&](int s, int kt) {
        const uint32_t stb = sbase + s * GSTAGE_B;
#pragma unroll
        for (int i = 0; i < 8; i++) {
            const int arr = i >> 1;
            int local = ((i & 1) << 8) + tid;       // 0..511
            int row = local >> 2;
            int c   = local & 3;
            uint32_t dst = stb + arr * GARR_B + row * 64 +
                           ((c ^ ((row >> 1) & 3)) << 4);
            const char* src = srcs[arr] + (size_t)row * (KDIM * 2) + kt * 64 + c * 16;
            CP16(dst, src);
        }
        CP_COMMIT();
    };

    // prologue: stages 0 and 1 in flight
    load_stage(0, 0);
    load_stage(1, 1);

    for (int kt = 0; kt < NKT; kt++) {
        const int s = kt % 3;
        if (kt + 1 < NKT) {
            asm volatile("cp.async.wait_group 1;");
        } else {
            asm volatile("cp.async.wait_group 0;");
        }
        __syncthreads();
        // load kt+2 into the buffer compute(kt-1) used; barrier above makes it safe
        if (kt + 2 < NKT) load_stage((kt + 2) % 3, kt + 2);

        const uint32_t AbO = sbase + s * GSTAGE_B;
        const uint32_t AsO = AbO + GARR_B;
        const uint32_t BbO = AbO + 2 * GARR_B;
        const uint32_t BsO = AbO + 3 * GARR_B;

#pragma unroll
        for (int ks = 0; ks < 2; ks++) {
            const int cA = ks * 2 + (m_ >> 1);
            const int cB = ks * 2 + (m_ & 1);

            uint32_t bb[4][2], bs[4][2];
#pragma unroll
            for (int p = 0; p < 2; p++) {
                uint32_t off = brow[p] * 64 + ((cB ^ bsw[p]) << 4);
                uint32_t r[4], r2[4];
                ldm4(BbO + off, r);
                ldm4(BsO + off, r2);
                bb[2 * p][0] = r[0];  bb[2 * p][1] = r[1];
                bb[2 * p + 1][0] = r[2]; bb[2 * p + 1][1] = r[3];
                bs[2 * p][0] = r2[0]; bs[2 * p][1] = r2[1];
                bs[2 * p + 1][0] = r2[2]; bs[2 * p + 1][1] = r2[3];
            }
#pragma unroll
            for (int mt = 0; mt < 4; mt++) {
                uint32_t off = arow[mt] * 64 + ((cA ^ asw[mt]) << 4);
                uint32_t ab[4], asf[4];
                ldm4(AbO + off, ab);
                ldm4(AsO + off, asf);
#pragma unroll
                for (int nt = 0; nt < 4; nt++) {
                    mma_bf16(acc[mt][nt], ab,  bb[nt][0], bb[nt][1]);
                    mma_bf16(acc[mt][nt], ab,  bs[nt][0], bs[nt][1]);
                    mma_bf16(acc[mt][nt], asf, bb[nt][0], bb[nt][1]);
                }
            }
        }
    }

    // ---- epilogue ----
#pragma unroll
    for (int mt = 0; mt < 4; mt++) {
#pragma unroll
        for (int nt = 0; nt < 4; nt++) {
            const int r  = m0 + wm * 64 + mt * 16 + g;
            const int cc = n0 + wn * 32 + nt * 8 + 2 * t4;
            if (MODE == 1) {
                size_t i0 = (size_t)r * Ncols + cc;
                *(float2*)&C[i0] = make_float2(acc[mt][nt][0], acc[mt][nt][1]);
                *(float2*)&C[i0 + (size_t)8 * Ncols] =
                    make_float2(acc[mt][nt][2], acc[mt][nt][3]);
            } else {
                float v0 = acc[mt][nt][0], v1 = acc[mt][nt][1];
                float v2 = acc[mt][nt][2], v3 = acc[mt][nt][3];
                float b0 = __bfloat162float(__float2bfloat16(v0));
                float b1 = __bfloat162float(__float2bfloat16(v1));
                float b2 = __bfloat162float(__float2bfloat16(v2));
                float b3 = __bfloat162float(__float2bfloat16(v3));
                const int sec = cc >> 10;
                const int c10 = cc & 1023;
                const int h   = c10 >> 6;
                const int d0  = c10 & 63;
                const int b   = r >> 11;
                const int sl  = r & 2047;
                if (sec < 2) {
                    __nv_bfloat16* db = (sec == 0) ? g_qb : g_kb;
                    __nv_bfloat16* ds = (sec == 0) ? g_qs : g_ks;
                    size_t i0 = (((size_t)(b * HH + h)) * SS + sl) * DD + d0;
                    *(uint32_t*)&db[i0] = packbf(b0, b1);
                    *(uint32_t*)&ds[i0] = packbf(v0 - b0, v1 - b1);
                    *(uint32_t*)&db[i0 + 8 * DD] = packbf(b2, b3);
                    *(uint32_t*)&ds[i0 + 8 * DD] = packbf(v2 - b2, v3 - b3);
                } else {
                    size_t base = ((size_t)(b * HH + h)) * DD * SS;
                    size_t iA = base + (size_t)d0 * SS + sl;
                    size_t iB = base + (size_t)(d0 + 1) * SS + sl;
                    g_vb[iA]     = __float2bfloat16(b0);
                    g_vs[iA]     = __float2bfloat16(v0 - b0);
                    g_vb[iB]     = __float2bfloat16(b1);
                    g_vs[iB]     = __float2bfloat16(v1 - b1);
                    g_vb[iA + 8] = __float2bfloat16(b2);
                    g_vs[iA + 8] = __float2bfloat16(v2 - b2);
                    g_vb[iB + 8] = __float2bfloat16(b3);
                    g_vs[iB + 8] = __float2bfloat16(v3 - b3);
                }
            }
        }
    }
}

// ---------------------------------------------------------------------------
// Tensor-core flash attention with ldmatrix + double-buffered K/V +
// mma-granularity causal skipping.
// ---------------------------------------------------------------------------
#define FQ_B   16384
#define FARR_B 8192
#define FSTAGE_B (4 * FARR_B)              // 32768
#define FLASH_SMEM (2 * FQ_B + 2 * FSTAGE_B)   // 98304

__global__ __launch_bounds__(256, 2) void flash_tc(void)
{
    extern __shared__ uint32_t fw4[];
    const uint32_t sbase = sm2u32(fw4);

    const int tid  = threadIdx.x;
    const int lane = tid & 31;
    const int g    = lane >> 2;
    const int t4   = lane & 3;
    const int m_   = lane >> 3;
    const int j_   = lane & 7;
    const int w    = tid >> 5;
    const int qt   = blockIdx.x;
    const int bh   = blockIdx.y;
    const int q0   = qt * 128;
    const int b    = bh >> 4, h = bh & 15;

    const char* qb_src = (const char*)(g_qb + ((size_t)bh * SS + q0) * DD);
    const char* qs_src = (const char*)(g_qs + ((size_t)bh * SS + q0) * DD);
    const char* kb_base = (const char*)(g_kb + (size_t)bh * SS * DD);
    const char* ks_base = (const char*)(g_ks + (size_t)bh * SS * DD);
    const char* vb_base = (const char*)(g_vb + (size_t)bh * DD * SS);
    const char* vs_base = (const char*)(g_vs + (size_t)bh * DD * SS);

    const int qrow_l = 16 * w + ((m_ & 1) << 3) + j_;
    const int qsw    = qrow_l & 7;
    int krow[4], ksw[4];
#pragma unroll
    for (int p = 0; p < 4; p++) {
        krow[p] = p * 16 + ((m_ >> 1) << 3) + j_;
        ksw[p]  = krow[p] & 7;
    }

    // ---- prologue loads: Q + KV stage 0 ----
#pragma unroll
    for (int i = 0; i < 8; i++) {
        const int arr = i >> 2;
        int local = ((i & 3) << 8) + tid;
        int row = local >> 3, c = local & 7;
        uint32_t dst = sbase + arr * FQ_B + row * 128 + ((c ^ (row & 7)) << 4);
        const char* src = (arr ? qs_src : qb_src) + (size_t)row * 128 + c * 16;
        CP16(dst, src);
    }
#pragma unroll
    for (int i = 0; i < 8; i++) {
        const int arr = i >> 1;
        int local = ((i & 1) << 8) + tid;
        int row = local >> 3, c = local & 7;
        uint32_t dst = sbase + 2 * FQ_B + arr * FARR_B + row * 128 +
                       ((c ^ (row & 7)) << 4);
        const char* src;
        if (arr == 0)      src = kb_base + (size_t)row * 128 + c * 16;
        else if (arr == 1) src = ks_base + (size_t)row * 128 + c * 16;
        else if (arr == 2) src = vb_base + (size_t)row * (SS * 2) + c * 16;
        else               src = vs_base + (size_t)row * (SS * 2) + c * 16;
        CP16(dst, src);
    }
    CP_COMMIT();

    float s4[8][4], y[8][4];
#pragma unroll
    for (int j = 0; j < 8; j++)
#pragma unroll
        for (int e = 0; e < 4; e++) y[j][e] = 0.0f;
    float m0 = -1e30f, m1 = -1e30f, l0 = 0.0f, l1 = 0.0f;

    const int qrow0 = q0 + 16 * w + g;
    const int qlim  = q0 + 16 * w + 15;     // max row this warp owns
    const int jmax  = 2 * qt + 2;

    for (int jt = 0; jt < jmax; jt++) {
        const int s  = jt & 1;
        const int k0 = jt * 64;

        if (jt + 1 < jmax) {
            const int kn = (jt + 1) * 64;
            const uint32_t stb = sbase + 2 * FQ_B + (s ^ 1) * FSTAGE_B;
#pragma unroll
            for (int i = 0; i < 8; i++) {
                const int arr = i >> 1;
                int local = ((i & 1) << 8) + tid;
                int row = local >> 3, c = local & 7;
                uint32_t dst = stb + arr * FARR_B + row * 128 + ((c ^ (row & 7)) << 4);
                const char* src;
                if (arr == 0)      src = kb_base + ((size_t)(kn + row)) * 128 + c * 16;
                else if (arr == 1) src = ks_base + ((size_t)(kn + row)) * 128 + c * 16;
                else if (arr == 2) src = vb_base + (size_t)row * (SS * 2) + kn * 2 + c * 16;
                else               src = vs_base + (size_t)row * (SS * 2) + kn * 2 + c * 16;
                CP16(dst, src);
            }
            CP_COMMIT();
            asm volatile("cp.async.wait_group 1;");
        } else {
            asm volatile("cp.async.wait_group 0;");
        }
        __syncthreads();

        const bool active = (k0 <= qlim);
        if (active) {
            const uint32_t KbO = sbase + 2 * FQ_B + s * FSTAGE_B;
            const uint32_t KsO = KbO + FARR_B;
            const uint32_t VbO = KbO + 2 * FARR_B;
            const uint32_t VsO = KbO + 3 * FARR_B;

            // ---- S = Q K^T (3-split), skipping fully-masked 16-key pairs ----
#pragma unroll
            for (int j = 0; j < 8; j++)
#pragma unroll
                for (int e = 0; e < 4; e++) s4[j][e] = 0.0f;

#pragma unroll
            for (int ks = 0; ks < 4; ks++) {
                const int cA = ks * 2 + (m_ >> 1);
                const int cB = ks * 2 + (m_ & 1);
                uint32_t qoff = qrow_l * 128 + ((cA ^ qsw) << 4);
                uint32_t ab[4], asf[4];
                ldm4(sbase + qoff, ab);
                ldm4(sbase + FQ_B + qoff, asf);
#pragma unroll
                for (int p = 0; p < 4; p++) {
                    if (k0 + p * 16 <= qlim) {      // warp-uniform causal skip
                        uint32_t off = krow[p] * 128 + ((cB ^ ksw[p]) << 4);
                        uint32_t rb[4], rs[4];
                        ldm4(KbO + off, rb);
                        ldm4(KsO + off, rs);
                        mma_bf16(s4[2 * p],     ab,  rb[0], rb[1]);
                        mma_bf16(s4[2 * p],     ab,  rs[0], rs[1]);
                        mma_bf16(s4[2 * p],     asf, rb[0], rb[1]);
                        mma_bf16(s4[2 * p + 1], ab,  rb[2], rb[3]);
                        mma_bf16(s4[2 * p + 1], ab,  rs[2], rs[3]);
                        mma_bf16(s4[2 * p + 1], asf, rb[2], rb[3]);
                    }
                }
            }

            // ---- scale + causal mask ----
#pragma unroll
            for (int j = 0; j < 8; j++)
#pragma unroll
                for (int e = 0; e < 4; e++) s4[j][e] *= 0.125f;
            if (k0 + 63 > q0 + 16 * w) {
#pragma unroll
                for (int nt = 0; nt < 8; nt++) {
                    int kg = k0 + nt * 8 + 2 * t4;
#pragma unroll
                    for (int e = 0; e < 4; e++) {
                        int kk = kg + (e & 1);
                        int qq = qrow0 + ((e >> 1) << 3);
                        if (kk > qq) s4[nt][e] = -1e30f;
                    }
                }
            }

            // ---- online softmax ----
            float mx0 = -1e30f, mx1 = -1e30f;
#pragma unroll
            for (int j = 0; j < 8; j++) {
                mx0 = fmaxf(mx0, fmaxf(s4[j][0], s4[j][1]));
                mx1 = fmaxf(mx1, fmaxf(s4[j][2], s4[j][3]));
            }
            mx0 = fmaxf(mx0, __shfl_xor_sync(0xffffffffu, mx0, 1));
            mx0 = fmaxf(mx0, __shfl_xor_sync(0xffffffffu, mx0, 2));
            mx1 = fmaxf(mx1, __shfl_xor_sync(0xffffffffu, mx1, 1));
            mx1 = fmaxf(mx1, __shfl_xor_sync(0xffffffffu, mx1, 2));
            float mn0 = fmaxf(m0, mx0), mn1 = fmaxf(m1, mx1);
            float c0 = __expf(m0 - mn0), c1 = __expf(m1 - mn1);
            m0 = mn0; m1 = mn1;
            float sum0 = 0.0f, sum1 = 0.0f;
#pragma unroll
            for (int j = 0; j < 8; j++) {
                s4[j][0] = __expf(s4[j][0] - mn0); sum0 += s4[j][0];
                s4[j][1] = __expf(s4[j][1] - mn0); sum0 += s4[j][1];
                s4[j][2] = __expf(s4[j][2] - mn1); sum1 += s4[j][2];
                s4[j][3] = __expf(s4[j][3] - mn1); sum1 += s4[j][3];
            }
            sum0 += __shfl_xor_sync(0xffffffffu, sum0, 1);
            sum0 += __shfl_xor_sync(0xffffffffu, sum0, 2);
            sum1 += __shfl_xor_sync(0xffffffffu, sum1, 1);
            sum1 += __shfl_xor_sync(0xffffffffu, sum1, 2);
            l0 = l0 * c0 + sum0;
            l1 = l1 * c1 + sum1;
#pragma unroll
            for (int j = 0; j < 8; j++) {
                y[j][0] *= c0; y[j][1] *= c0;
                y[j][2] *= c1; y[j][3] *= c1;
            }

            // ---- Y += P V (3-split, P register-resident), with causal skip ----
#pragma unroll
            for (int kk = 0; kk < 4; kk++) {
                if (k0 + kk * 16 <= qlim) {          // warp-uniform: P=0 beyond
                    float p00 = s4[2 * kk][0],     p01 = s4[2 * kk][1];
                    float p10 = s4[2 * kk][2],     p11 = s4[2 * kk][3];
                    float p20 = s4[2 * kk + 1][0], p21 = s4[2 * kk + 1][1];
                    float p30 = s4[2 * kk + 1][2], p31 = s4[2 * kk + 1][3];
                    float b00 = __bfloat162float(__float2bfloat16(p00));
                    float b01 = __bfloat162float(__float2bfloat16(p01));
                    float b10 = __bfloat162float(__float2bfloat16(p10));
                    float b11 = __bfloat162float(__float2bfloat16(p11));
                    float b20 = __bfloat162float(__float2bfloat16(p20));
                    float b21 = __bfloat162float(__float2bfloat16(p21));
                    float b30 = __bfloat162float(__float2bfloat16(p30));
                    float b31 = __bfloat162float(__float2bfloat16(p31));
                    uint32_t pab[4] = { packbf(b00, b01), packbf(b10, b11),
                                        packbf(b20, b21), packbf(b30, b31) };
                    uint32_t pas[4] = { packbf(p00 - b00, p01 - b01),
                                        packbf(p10 - b10, p11 - b11),
                                        packbf(p20 - b20, p21 - b21),
                                        packbf(p30 - b30, p31 - b31) };
                    const int cV = kk * 2 + (m_ & 1);
#pragma unroll
                    for (int p = 0; p < 4; p++) {
                        uint32_t off = krow[p] * 128 + ((cV ^ ksw[p]) << 4);
                        uint32_t rv[4], rvs[4];
                        ldm4(VbO + off, rv);
                        ldm4(VsO + off, rvs);
                        mma_bf16(y[2 * p],     pab, rv[0],  rv[1]);
                        mma_bf16(y[2 * p],     pab, rvs[0], rvs[1]);
                        mma_bf16(y[2 * p],     pas, rv[0],  rv[1]);
                        mma_bf16(y[2 * p + 1], pab, rv[2],  rv[3]);
                        mma_bf16(y[2 * p + 1], pab, rvs[2], rvs[3]);
                        mma_bf16(y[2 * p + 1], pas, rv[2],  rv[3]);
                    }
                }
            }
        }
        __syncthreads();
    }

    // ---- normalize + write bf16-split y ----
    float inv0 = 1.0f / l0, inv1 = 1.0f / l1;
    const size_t row0 = (size_t)b * SS + q0 + 16 * w + g;
    const size_t row1 = row0 + 8;
#pragma unroll
    for (int nd = 0; nd < 8; nd++) {
        int col = h * 64 + nd * 8 + 2 * t4;
        float v0 = y[nd][0] * inv0, v1 = y[nd][1] * inv0;
        float v2 = y[nd][2] * inv1, v3 = y[nd][3] * inv1;
        float b0 = __bfloat162float(__float2bfloat16(v0));
        float b1 = __bfloat162float(__float2bfloat16(v1));
        float b2 = __bfloat162float(__float2bfloat16(v2));
        float b3 = __bfloat162float(__float2bfloat16(v3));
        size_t i0 = row0 * EE + col, i1 = row1 * EE + col;
        *(uint32_t*)&g_yb[i0] = packbf(b0, b1);
        *(uint32_t*)&g_ys[i0] = packbf(v0 - b0, v1 - b1);
        *(uint32_t*)&g_yb[i1] = packbf(b2, b3);
        *(uint32_t*)&g_ys[i1] = packbf(v2 - b2, v3 - b3);
    }
}

// ---------------------------------------------------------------------------
extern "C" void kernel_launch(void* const* d_in, const int* in_sizes, int n_in,
                              void* d_out, int out_size)
{
    const float* x      = (const float*)d_in[0];
    const float* w_attn = (const float*)d_in[1];
    const float* w_proj = (const float*)d_in[2];
    float* out = (float*)d_out;

    __nv_bfloat16 *xb, *xs, *wab, *was, *wpb, *wps, *yb, *ys;
    cudaGetSymbolAddress((void**)&xb,  g_xb);
    cudaGetSymbolAddress((void**)&xs,  g_xs);
    cudaGetSymbolAddress((void**)&wab, g_wab);
    cudaGetSymbolAddress((void**)&was, g_was);
    cudaGetSymbolAddress((void**)&wpb, g_wpb);
    cudaGetSymbolAddress((void**)&wps, g_wps);
    cudaGetSymbolAddress((void**)&yb,  g_yb);
    cudaGetSymbolAddress((void**)&ys,  g_ys);

    cudaFuncSetAttribute(bf_gemm<0>, cudaFuncAttributeMaxDynamicSharedMemorySize, GEMM_DSMEM);
    cudaFuncSetAttribute(bf_gemm<1>, cudaFuncAttributeMaxDynamicSharedMemorySize, GEMM_DSMEM);
    cudaFuncSetAttribute(flash_tc,   cudaFuncAttributeMaxDynamicSharedMemorySize, FLASH_SMEM);

    // 0. split x; transpose+split weights
    {
        int n4 = M_TOT * EE / 4;
        split_kernel<<<(n4 + 255) / 256, 256>>>(x, xb, xs, n4);
        dim3 tb(32, 8);
        transpose_split_kernel<<<dim3(3 * EE / 32, EE / 32), tb>>>(w_attn, wab, was, EE, 3 * EE);
        transpose_split_kernel<<<dim3(EE / 32, EE / 32), tb>>>(w_proj, wpb, wps, EE, EE);
    }

    // 1. QKV GEMM -> bf16-split q/k/v (v transposed)
    {
        dim3 grid(3 * EE / 128, M_TOT / 128);   // (24, 64)
        bf_gemm<0><<<grid, 256, GEMM_DSMEM>>>(xb, xs, wab, was, nullptr, 3 * EE);
    }

    // 2. flash attention -> bf16-split y
    {
        dim3 grid(SS / 128, BB * HH);           // (16, 64)
        flash_tc<<<grid, 256, FLASH_SMEM>>>();
    }

    // 3. proj GEMM -> out (fp32)
    {
        dim3 grid(EE / 128, M_TOT / 128);       // (8, 64)
        bf_gemm<1><<<grid, 256, GEMM_DSMEM>>>(yb, ys, wpb, wps, out, EE);
    }
}